// round 5
// baseline (speedup 1.0000x reference)
#include <cuda_runtime.h>
#include <math.h>

#define GNODES 50000
#define DSTALK 3
#define HCH 64
#define IN_DIM 256
#define OUT_DIM 40
#define NLAYERS 4
#define NNZ_E 2400000
#define NEXT (GNODES * DSTALK)   // 150000

#define SCAN_BS 512
#define SCAN_NB ((NEXT + SCAN_BS - 1) / SCAN_BS)   // 293

// ---------------- scratch (static device globals; no allocs) ----------------
__device__ float g_HH[NEXT * HCH];    // h (== h0 between layers), [G,192] view
__device__ float g_T[NEXT * HCH];     // Tl = leftmix(HH)
__device__ int    g_cnt[NEXT];
__device__ int    g_rowptr[NEXT + 1];
__device__ int    g_tmp[NEXT];
__device__ int    g_bsum[SCAN_NB];
__device__ float2 g_epack[NNZ_E];     // packed (col_bits, val) per edge (CSR order)

// ---------------- lin1: g_HH = elu(x @ W1^T + b1) ---------------------------
__global__ __launch_bounds__(256) void lin1_kernel(const float* __restrict__ x,
                                                   const float* __restrict__ w,
                                                   const float* __restrict__ b) {
    __shared__ float As[16][132];
    __shared__ float Bs[16][68];
    const int bm = blockIdx.x * 128;
    const int bn = blockIdx.y * 64;
    const int tid = threadIdx.x;
    const int tx = tid & 15;
    const int ty = tid >> 4;

    float acc[8][4];
#pragma unroll
    for (int i = 0; i < 8; i++)
#pragma unroll
        for (int j = 0; j < 4; j++) acc[i][j] = 0.f;

    const int lrA = tid >> 1;
    const int lkA = (tid & 1) * 8;
    const int lrB = tid >> 2;
    const int lkB = (tid & 3) * 4;

    for (int k0 = 0; k0 < IN_DIM; k0 += 16) {
        float4 a0 = make_float4(0.f, 0.f, 0.f, 0.f);
        float4 a1 = make_float4(0.f, 0.f, 0.f, 0.f);
        int gr = bm + lrA;
        if (gr < GNODES) {
            a0 = *(const float4*)&x[gr * IN_DIM + k0 + lkA];
            a1 = *(const float4*)&x[gr * IN_DIM + k0 + lkA + 4];
        }
        As[lkA + 0][lrA] = a0.x; As[lkA + 1][lrA] = a0.y;
        As[lkA + 2][lrA] = a0.z; As[lkA + 3][lrA] = a0.w;
        As[lkA + 4][lrA] = a1.x; As[lkA + 5][lrA] = a1.y;
        As[lkA + 6][lrA] = a1.z; As[lkA + 7][lrA] = a1.w;

        float4 bv = *(const float4*)&w[(bn + lrB) * IN_DIM + k0 + lkB];
        Bs[lkB + 0][lrB] = bv.x; Bs[lkB + 1][lrB] = bv.y;
        Bs[lkB + 2][lrB] = bv.z; Bs[lkB + 3][lrB] = bv.w;
        __syncthreads();

#pragma unroll
        for (int k = 0; k < 16; k++) {
            float4 ar0 = *(float4*)&As[k][ty * 8];
            float4 ar1 = *(float4*)&As[k][ty * 8 + 4];
            float4 br  = *(float4*)&Bs[k][tx * 4];
            float ar[8] = {ar0.x, ar0.y, ar0.z, ar0.w, ar1.x, ar1.y, ar1.z, ar1.w};
            float brr[4] = {br.x, br.y, br.z, br.w};
#pragma unroll
            for (int i = 0; i < 8; i++)
#pragma unroll
                for (int j = 0; j < 4; j++) acc[i][j] += ar[i] * brr[j];
        }
        __syncthreads();
    }

    float4 bias = *(const float4*)&b[bn + tx * 4];
    float bb[4] = {bias.x, bias.y, bias.z, bias.w};
#pragma unroll
    for (int i = 0; i < 8; i++) {
        int gr = bm + ty * 8 + i;
        if (gr >= GNODES) continue;
        float4 r;
        float v;
        v = acc[i][0] + bb[0]; r.x = (v > 0.f) ? v : (expf(v) - 1.f);
        v = acc[i][1] + bb[1]; r.y = (v > 0.f) ? v : (expf(v) - 1.f);
        v = acc[i][2] + bb[2]; r.z = (v > 0.f) ? v : (expf(v) - 1.f);
        v = acc[i][3] + bb[3]; r.w = (v > 0.f) ? v : (expf(v) - 1.f);
        *(float4*)&g_HH[gr * 192 + bn + tx * 4] = r;
    }
}

// ---------------- leftmix: g_T = Ml(g_HH)  (3x3 stalk mix) ------------------
__global__ __launch_bounds__(256) void leftmix_kernel(const float* __restrict__ lw) {
    int idx = blockIdx.x * 256 + threadIdx.x;   // over GNODES*16
    if (idx >= GNODES * 16) return;
    int g = idx >> 4, c4 = idx & 15;
    const float4* HH4 = (const float4*)g_HH;
    float4* T4 = (float4*)g_T;
    float L[9];
#pragma unroll
    for (int i = 0; i < 9; i++) L[i] = __ldg(&lw[i]);
    float4 h0 = HH4[(3 * g + 0) * 16 + c4];
    float4 h1 = HH4[(3 * g + 1) * 16 + c4];
    float4 h2 = HH4[(3 * g + 2) * 16 + c4];
#pragma unroll
    for (int d = 0; d < 3; d++) {
        float w0 = L[3 * d], w1 = L[3 * d + 1], w2 = L[3 * d + 2];
        float4 t;
        t.x = w0 * h0.x + w1 * h1.x + w2 * h2.x;
        t.y = w0 * h0.y + w1 * h1.y + w2 * h2.y;
        t.z = w0 * h0.z + w1 * h1.z + w2 * h2.z;
        t.w = w0 * h0.w + w1 * h1.w + w2 * h2.w;
        T4[(3 * g + d) * 16 + c4] = t;
    }
}

// ---------------- CSR build: zero / hist / scan / scatter -------------------
__global__ __launch_bounds__(256) void zero_cnt_kernel() {
    int i = blockIdx.x * blockDim.x + threadIdx.x;
    if (i < NEXT) g_cnt[i] = 0;
}

__global__ __launch_bounds__(256) void hist_kernel(const int* __restrict__ rows) {
    int i = blockIdx.x * blockDim.x + threadIdx.x;
    if (i >= NNZ_E / 4) return;
    int4 r = ((const int4*)rows)[i];
    atomicAdd(&g_cnt[r.x], 1);
    atomicAdd(&g_cnt[r.y], 1);
    atomicAdd(&g_cnt[r.z], 1);
    atomicAdd(&g_cnt[r.w], 1);
}

__global__ __launch_bounds__(SCAN_BS) void scan1_kernel() {
    __shared__ int s[SCAN_BS];
    int t = threadIdx.x;
    int i = blockIdx.x * SCAN_BS + t;
    int v = (i < NEXT) ? g_cnt[i] : 0;
    s[t] = v;
    __syncthreads();
#pragma unroll
    for (int off = 1; off < SCAN_BS; off <<= 1) {
        int x = (t >= off) ? s[t - off] : 0;
        __syncthreads();
        s[t] += x;
        __syncthreads();
    }
    if (i < NEXT) g_rowptr[i] = s[t] - v;
    if (t == SCAN_BS - 1) g_bsum[blockIdx.x] = s[t];
}

__global__ __launch_bounds__(SCAN_BS) void scan2_kernel() {
    __shared__ int s[SCAN_BS];
    int t = threadIdx.x;
    int v = (t < SCAN_NB) ? g_bsum[t] : 0;
    s[t] = v;
    __syncthreads();
#pragma unroll
    for (int off = 1; off < SCAN_BS; off <<= 1) {
        int x = (t >= off) ? s[t - off] : 0;
        __syncthreads();
        s[t] += x;
        __syncthreads();
    }
    if (t < SCAN_NB) g_bsum[t] = s[t] - v;
}

__global__ __launch_bounds__(256) void scan3_kernel() {
    int i = blockIdx.x * blockDim.x + threadIdx.x;
    if (i < NEXT) {
        int rp = g_rowptr[i] + g_bsum[i / SCAN_BS];
        g_rowptr[i] = rp;
        g_tmp[i] = rp;
    }
    if (i == 0) g_rowptr[NEXT] = NNZ_E;
}

__global__ __launch_bounds__(256) void scatter_kernel(const int* __restrict__ rows,
                                                      const int* __restrict__ cols,
                                                      const float* __restrict__ vals) {
    int i = blockIdx.x * blockDim.x + threadIdx.x;
    if (i >= NNZ_E / 4) return;
    int4 r = ((const int4*)rows)[i];
    int4 c = ((const int4*)cols)[i];
    float4 v = ((const float4*)vals)[i];
    int p;
    p = atomicAdd(&g_tmp[r.x], 1); g_epack[p] = make_float2(__int_as_float(c.x), v.x);
    p = atomicAdd(&g_tmp[r.y], 1); g_epack[p] = make_float2(__int_as_float(c.y), v.y);
    p = atomicAdd(&g_tmp[r.z], 1); g_epack[p] = make_float2(__int_as_float(c.z), v.z);
    p = atomicAdd(&g_tmp[r.w], 1); g_epack[p] = make_float2(__int_as_float(c.w), v.w);
}

// ------- fused SpMM + (@ R^T) + epilogue ------------------------------------
// acc_row = Σ_e v_e · Tl[c_e,:]          (pull gather, half-warp per row)
// h'      = acc_row @ R^T                 (in-block 64x64, hidden under gather)
// HH[row] = gate·HH[row] − elu(h')
__global__ __launch_bounds__(512) void spmm_fused_kernel(const float* __restrict__ rightw,
                                                         const float* __restrict__ eps, int l) {
    __shared__ float sRt[64 * 68];   // Rt[c][cp] = R[cp][c]
    __shared__ float sacc[32 * 68];
    __shared__ float sgate[3];
    const int tid = threadIdx.x;

    for (int i = tid; i < 4096; i += 512) {
        int c = i >> 6, cp = i & 63;
        sRt[c * 68 + cp] = __ldg(&rightw[cp * 64 + c]);
    }
    if (tid < 3) sgate[tid] = 1.f + tanhf(__ldg(&eps[l * 3 + tid]));

    const int lrow = tid >> 4;   // 0..31
    const int hl = tid & 15;
    const float4* __restrict__ T4 = (const float4*)g_T;
    float4* HH4 = (float4*)g_HH;

    for (int t0 = blockIdx.x * 32; t0 < NEXT; t0 += gridDim.x * 32) {
        int row = t0 + lrow;
        bool valid = row < NEXT;

        float4 acc = make_float4(0.f, 0.f, 0.f, 0.f);
        if (valid) {
            int s = __ldg(&g_rowptr[row]);
            int e = __ldg(&g_rowptr[row + 1]);
            int k = s;
            float4 acc2 = make_float4(0.f, 0.f, 0.f, 0.f);
            for (; k + 3 < e; k += 4) {
                float2 p0 = __ldg(&g_epack[k]);
                float2 p1 = __ldg(&g_epack[k + 1]);
                float2 p2 = __ldg(&g_epack[k + 2]);
                float2 p3 = __ldg(&g_epack[k + 3]);
                float4 t0v = __ldg(&T4[__float_as_int(p0.x) * 16 + hl]);
                float4 t1v = __ldg(&T4[__float_as_int(p1.x) * 16 + hl]);
                float4 t2v = __ldg(&T4[__float_as_int(p2.x) * 16 + hl]);
                float4 t3v = __ldg(&T4[__float_as_int(p3.x) * 16 + hl]);
                acc.x += p0.y * t0v.x + p1.y * t1v.x;
                acc.y += p0.y * t0v.y + p1.y * t1v.y;
                acc.z += p0.y * t0v.z + p1.y * t1v.z;
                acc.w += p0.y * t0v.w + p1.y * t1v.w;
                acc2.x += p2.y * t2v.x + p3.y * t3v.x;
                acc2.y += p2.y * t2v.y + p3.y * t3v.y;
                acc2.z += p2.y * t2v.z + p3.y * t3v.z;
                acc2.w += p2.y * t2v.w + p3.y * t3v.w;
            }
            for (; k < e; k++) {
                float2 p0 = __ldg(&g_epack[k]);
                float4 t0v = __ldg(&T4[__float_as_int(p0.x) * 16 + hl]);
                acc.x += p0.y * t0v.x;
                acc.y += p0.y * t0v.y;
                acc.z += p0.y * t0v.z;
                acc.w += p0.y * t0v.w;
            }
            acc.x += acc2.x; acc.y += acc2.y; acc.z += acc2.z; acc.w += acc2.w;
        }

        __syncthreads();   // previous tile's GEMM reads of sacc complete
        *(float4*)&sacc[lrow * 68 + hl * 4] = acc;
        __syncthreads();

        if (valid) {
            // o[cp4] = Σ_c sacc[lrow][c] * Rt[c][cp4..+3]
            float4 o = make_float4(0.f, 0.f, 0.f, 0.f);
            const float* ar = &sacc[lrow * 68];
#pragma unroll 8
            for (int c = 0; c < 64; c++) {
                float a = ar[c];                              // half-warp broadcast
                float4 r4 = *(float4*)&sRt[c * 68 + hl * 4];
                o.x += a * r4.x; o.y += a * r4.y;
                o.z += a * r4.z; o.w += a * r4.w;
            }
            float gate = sgate[row % 3];
            float4 h = HH4[row * 16 + hl];
            float ex, ey, ez, ew;
            ex = (o.x > 0.f) ? o.x : (expf(o.x) - 1.f);
            ey = (o.y > 0.f) ? o.y : (expf(o.y) - 1.f);
            ez = (o.z > 0.f) ? o.z : (expf(o.z) - 1.f);
            ew = (o.w > 0.f) ? o.w : (expf(o.w) - 1.f);
            float4 r;
            r.x = gate * h.x - ex;
            r.y = gate * h.y - ey;
            r.z = gate * h.z - ez;
            r.w = gate * h.w - ew;
            HH4[row * 16 + hl] = r;
        }
    }
}

// ---------------- lin2 + log_softmax ----------------------------------------
__global__ __launch_bounds__(256) void out_kernel(const float* __restrict__ w2,
                                                  const float* __restrict__ b2,
                                                  float* __restrict__ out) {
    __shared__ float sW[40 * 193];
    __shared__ float sH[16 * 192];
    const int tid = threadIdx.x;
    const int gbase = blockIdx.x * 16;

    for (int i = tid; i < 40 * 192; i += 256)
        sW[(i / 192) * 193 + (i % 192)] = w2[i];
    for (int i = tid; i < 16 * 192; i += 256)
        sH[i] = g_HH[gbase * 192 + i];
    __syncthreads();

    const int warp = tid >> 5, lane = tid & 31;
#pragma unroll
    for (int rr = 0; rr < 2; rr++) {
        int row = warp * 2 + rr;
        int g = gbase + row;
        float acc1 = 0.f, acc2 = 0.f;
        const float* hrow = &sH[row * 192];
#pragma unroll 8
        for (int j = 0; j < 192; j++) {
            float hv = hrow[j];
            acc1 += hv * sW[lane * 193 + j];
            if (lane < 8) acc2 += hv * sW[(lane + 32) * 193 + j];
        }
        acc1 += b2[lane];
        float v2 = (lane < 8) ? (acc2 + b2[lane + 32]) : -INFINITY;

        float m = fmaxf(acc1, v2);
#pragma unroll
        for (int off = 16; off; off >>= 1) m = fmaxf(m, __shfl_xor_sync(0xffffffffu, m, off));
        float s = expf(acc1 - m) + ((lane < 8) ? expf(v2 - m) : 0.f);
#pragma unroll
        for (int off = 16; off; off >>= 1) s += __shfl_xor_sync(0xffffffffu, s, off);
        float ls = m + logf(s);

        out[g * OUT_DIM + lane] = acc1 - ls;
        if (lane < 8) out[g * OUT_DIM + 32 + lane] = v2 - ls;
    }
}

// ---------------- launch -----------------------------------------------------
extern "C" void kernel_launch(void* const* d_in, const int* in_sizes, int n_in,
                              void* d_out, int out_size) {
    const float* x   = (const float*)d_in[0];
    const int*   lr  = (const int*)d_in[1];
    const int*   lc  = (const int*)d_in[2];
    const float* lv  = (const float*)d_in[3];
    const float* w1  = (const float*)d_in[4];
    const float* b1  = (const float*)d_in[5];
    const float* lw  = (const float*)d_in[6];   // [L,3,3]
    const float* rw  = (const float*)d_in[7];   // [L,64,64]
    const float* eps = (const float*)d_in[8];   // [L,3,1]
    const float* w2  = (const float*)d_in[9];
    const float* b2  = (const float*)d_in[10];
    float* out = (float*)d_out;

    lin1_kernel<<<dim3((GNODES + 127) / 128, 3), 256>>>(x, w1, b1);

    // CSR build (once; reused by all layers)
    zero_cnt_kernel<<<(NEXT + 255) / 256, 256>>>();
    hist_kernel<<<(NNZ_E / 4 + 255) / 256, 256>>>(lr);
    scan1_kernel<<<SCAN_NB, SCAN_BS>>>();
    scan2_kernel<<<1, SCAN_BS>>>();
    scan3_kernel<<<(NEXT + 255) / 256, 256>>>();
    scatter_kernel<<<(NNZ_E / 4 + 255) / 256, 256>>>(lr, lc, lv);

    for (int l = 0; l < NLAYERS; l++) {
        leftmix_kernel<<<(GNODES * 16 + 255) / 256, 256>>>(lw + l * 9);
        spmm_fused_kernel<<<1184, 512>>>(rw + l * 4096, eps, l);
    }
    out_kernel<<<GNODES / 16, 256>>>(w2, b2, out);
}

// round 6
// speedup vs baseline: 1.1633x; 1.1633x over previous
#include <cuda_runtime.h>
#include <cuda_bf16.h>
#include <math.h>

#define GNODES 50000
#define DSTALK 3
#define HCH 64
#define IN_DIM 256
#define OUT_DIM 40
#define NLAYERS 4
#define NNZ_E 2400000
#define NEXT (GNODES * DSTALK)   // 150000

#define SCAN_BS 512
#define SCAN_NB ((NEXT + SCAN_BS - 1) / SCAN_BS)   // 293

// ---------------- scratch (static device globals; no allocs) ----------------
__device__ float g_HH[NEXT * HCH];    // h (== h0 between layers), [G,192] view
__device__ float g_T[NEXT * HCH];     // post left+right transform
__device__ int    g_cnt[NEXT];
__device__ int    g_rowptr[NEXT + 1];
__device__ int    g_tmp[NEXT];
__device__ int    g_bsum[SCAN_NB];
__device__ float2 g_epack[NNZ_E];     // packed (col_bits, val) per edge (CSR order)
__device__ unsigned g_W1h[128 * 192]; // W1 split-hi, [kpair][n] pair-packed bf16x2
__device__ unsigned g_W1l[128 * 192]; // W1 split-lo

// ---------------- helpers ----------------------------------------------------
__device__ __forceinline__ void bf16_split2(float a, float b, unsigned& hi, unsigned& lo) {
    __nv_bfloat16 ah = __float2bfloat16(a);
    __nv_bfloat16 bh = __float2bfloat16(b);
    float ar = a - __bfloat162float(ah);
    float br = b - __bfloat162float(bh);
    __nv_bfloat16 al = __float2bfloat16(ar);
    __nv_bfloat16 bl = __float2bfloat16(br);
    hi = ((unsigned)__bfloat16_as_ushort(bh) << 16) | (unsigned)__bfloat16_as_ushort(ah);
    lo = ((unsigned)__bfloat16_as_ushort(bl) << 16) | (unsigned)__bfloat16_as_ushort(al);
}

#define MMA_BF16(d, a, b0, b1)                                              \
    asm volatile("mma.sync.aligned.m16n8k16.row.col.f32.bf16.bf16.f32 "     \
                 "{%0,%1,%2,%3}, {%4,%5,%6,%7}, {%8,%9}, {%0,%1,%2,%3};"    \
                 : "+f"(d[0]), "+f"(d[1]), "+f"(d[2]), "+f"(d[3])           \
                 : "r"(a[0]), "r"(a[1]), "r"(a[2]), "r"(a[3]), "r"(b0), "r"(b1))

// ---------------- W1 split prepass ------------------------------------------
__global__ __launch_bounds__(256) void wsplit_kernel(const float* __restrict__ w) {
    int i = blockIdx.x * 256 + threadIdx.x;    // over 128*192
    if (i >= 128 * 192) return;
    int kk = i / 192, n = i % 192;
    float a = w[n * IN_DIM + 2 * kk];
    float b = w[n * IN_DIM + 2 * kk + 1];
    unsigned hi, lo;
    bf16_split2(a, b, hi, lo);
    g_W1h[i] = hi;
    g_W1l[i] = lo;
}

// ---------------- lin1 (tensor cores, split-bf16): g_HH = elu(x@W1^T + b1) --
// BM=64, BN=64, BK=64. 256 threads = 8 warps (4 m-tiles x 2 n-halves).
__global__ __launch_bounds__(256) void lin1_tc_kernel(const float* __restrict__ x,
                                                      const float* __restrict__ b) {
    __shared__ unsigned sAh[64][33];
    __shared__ unsigned sAl[64][33];
    __shared__ unsigned sBh[32][65];
    __shared__ unsigned sBl[32][65];
    const int tid = threadIdx.x;
    const int warp = tid >> 5, lane = tid & 31;
    const int bm = blockIdx.x * 64, bn = blockIdx.y * 64;
    const int wm = (warp & 3) * 16;     // m offset of this warp
    const int wn = (warp >> 2) * 32;    // n offset of this warp

    float d[4][4];
#pragma unroll
    for (int j = 0; j < 4; j++)
#pragma unroll
        for (int i = 0; i < 4; i++) d[j][i] = 0.f;

    for (int k0 = 0; k0 < IN_DIM; k0 += 64) {
        // A tile: 64 rows x 64 k  (1024 float4)
        for (int i = tid; i < 1024; i += 256) {
            int r = i >> 4, f4 = i & 15;
            int gr = bm + r;
            float4 v = make_float4(0.f, 0.f, 0.f, 0.f);
            if (gr < GNODES) v = *(const float4*)&x[gr * IN_DIM + k0 + f4 * 4];
            unsigned h0, l0, h1, l1;
            bf16_split2(v.x, v.y, h0, l0);
            bf16_split2(v.z, v.w, h1, l1);
            sAh[r][f4 * 2] = h0;     sAh[r][f4 * 2 + 1] = h1;
            sAl[r][f4 * 2] = l0;     sAl[r][f4 * 2 + 1] = l1;
        }
        // B tile: 32 kpairs x 64 n (from precomputed split)
        for (int i = tid; i < 2048; i += 256) {
            int r = i >> 6, c = i & 63;
            int gi = (k0 / 2 + r) * 192 + bn + c;
            sBh[r][c] = g_W1h[gi];
            sBl[r][c] = g_W1l[gi];
        }
        __syncthreads();

#pragma unroll
        for (int ks = 0; ks < 4; ks++) {
            int ar0 = wm + (lane >> 2);
            int kp = ks * 8 + (lane & 3);
            unsigned ah[4] = { sAh[ar0][kp], sAh[ar0 + 8][kp],
                               sAh[ar0][kp + 4], sAh[ar0 + 8][kp + 4] };
            unsigned al[4] = { sAl[ar0][kp], sAl[ar0 + 8][kp],
                               sAl[ar0][kp + 4], sAl[ar0 + 8][kp + 4] };
#pragma unroll
            for (int j = 0; j < 4; j++) {
                int nc = wn + j * 8 + (lane >> 2);
                int kr = ks * 8 + (lane & 3);
                unsigned bh0 = sBh[kr][nc], bh1 = sBh[kr + 4][nc];
                unsigned bl0 = sBl[kr][nc], bl1 = sBl[kr + 4][nc];
                MMA_BF16(d[j], ah, bh0, bh1);
                MMA_BF16(d[j], ah, bl0, bl1);
                MMA_BF16(d[j], al, bh0, bh1);
            }
        }
        __syncthreads();
    }

    // epilogue: bias + elu + store
#pragma unroll
    for (int j = 0; j < 4; j++) {
        int c = bn + wn + j * 8 + (lane & 3) * 2;   // global n of d[j][0]
        float b0 = __ldg(&b[c]), b1 = __ldg(&b[c + 1]);
        int r0 = bm + wm + (lane >> 2);
        if (r0 < GNODES) {
            float v0 = d[j][0] + b0, v1 = d[j][1] + b1;
            v0 = (v0 > 0.f) ? v0 : (expf(v0) - 1.f);
            v1 = (v1 > 0.f) ? v1 : (expf(v1) - 1.f);
            *(float2*)&g_HH[r0 * 192 + c] = make_float2(v0, v1);
        }
        int r1 = r0 + 8;
        if (r1 < GNODES) {
            float v2 = d[j][2] + b0, v3 = d[j][3] + b1;
            v2 = (v2 > 0.f) ? v2 : (expf(v2) - 1.f);
            v3 = (v3 > 0.f) ? v3 : (expf(v3) - 1.f);
            *(float2*)&g_HH[r1 * 192 + c] = make_float2(v2, v3);
        }
    }
}

// ------- fused left(3x3 stalk) + right(64x64 channel) transform (R4) --------
__global__ __launch_bounds__(256) void transform_kernel(const float* __restrict__ leftw,
                                                        const float* __restrict__ rightw) {
    __shared__ float sh_h[48 * 68];
    __shared__ float sh_t[48 * 68];
    __shared__ float sh_R[64 * 68];
    const int tid = threadIdx.x;
    const int rowbase = blockIdx.x * 48;   // 3125 blocks * 48 = 150000 exact

    for (int i = tid; i < 1024; i += 256) {
        int row = i >> 4, c4 = i & 15;
        float4 v = ((const float4*)rightw)[i];
        *(float4*)&sh_R[row * 68 + c4 * 4] = v;
    }
    for (int i = tid; i < 768; i += 256) {
        int row = i >> 4, c4 = i & 15;
        float4 v = ((const float4*)g_HH)[(rowbase + row) * 16 + c4];
        *(float4*)&sh_h[row * 68 + c4 * 4] = v;
    }

    float Lw[9];
#pragma unroll
    for (int i = 0; i < 9; i++) Lw[i] = leftw[i];
    __syncthreads();

    for (int i = tid; i < 768; i += 256) {
        int row = i >> 4, c4 = i & 15;
        int e = row % 3;
        int gl = row - e;
        float4 h0 = *(float4*)&sh_h[(gl + 0) * 68 + c4 * 4];
        float4 h1 = *(float4*)&sh_h[(gl + 1) * 68 + c4 * 4];
        float4 h2 = *(float4*)&sh_h[(gl + 2) * 68 + c4 * 4];
        float w0 = Lw[e * 3 + 0], w1 = Lw[e * 3 + 1], w2 = Lw[e * 3 + 2];
        float4 t;
        t.x = w0 * h0.x + w1 * h1.x + w2 * h2.x;
        t.y = w0 * h0.y + w1 * h1.y + w2 * h2.y;
        t.z = w0 * h0.z + w1 * h1.z + w2 * h2.z;
        t.w = w0 * h0.w + w1 * h1.w + w2 * h2.w;
        *(float4*)&sh_t[row * 68 + c4 * 4] = t;
    }
    __syncthreads();

    const int cp = tid & 63;
    const int rg = tid >> 6;
    float acc[12];
#pragma unroll
    for (int i = 0; i < 12; i++) acc[i] = 0.f;
#pragma unroll
    for (int c0 = 0; c0 < 64; c0 += 4) {
        float4 rv = *(float4*)&sh_R[cp * 68 + c0];
#pragma unroll
        for (int i = 0; i < 12; i++) {
            float4 tv = *(float4*)&sh_t[(rg + 4 * i) * 68 + c0];
            acc[i] += tv.x * rv.x + tv.y * rv.y + tv.z * rv.z + tv.w * rv.w;
        }
    }
#pragma unroll
    for (int i = 0; i < 12; i++)
        g_T[(rowbase + rg + 4 * i) * 64 + cp] = acc[i];
}

// ---------------- CSR build: zero / hist / scan / scatter -------------------
__global__ __launch_bounds__(256) void zero_cnt_kernel() {
    int i = blockIdx.x * blockDim.x + threadIdx.x;
    if (i < NEXT) g_cnt[i] = 0;
}

__global__ __launch_bounds__(256) void hist_kernel(const int* __restrict__ rows) {
    int i = blockIdx.x * blockDim.x + threadIdx.x;
    if (i >= NNZ_E / 4) return;
    int4 r = ((const int4*)rows)[i];
    atomicAdd(&g_cnt[r.x], 1);
    atomicAdd(&g_cnt[r.y], 1);
    atomicAdd(&g_cnt[r.z], 1);
    atomicAdd(&g_cnt[r.w], 1);
}

__global__ __launch_bounds__(SCAN_BS) void scan1_kernel() {
    __shared__ int s[SCAN_BS];
    int t = threadIdx.x;
    int i = blockIdx.x * SCAN_BS + t;
    int v = (i < NEXT) ? g_cnt[i] : 0;
    s[t] = v;
    __syncthreads();
#pragma unroll
    for (int off = 1; off < SCAN_BS; off <<= 1) {
        int x = (t >= off) ? s[t - off] : 0;
        __syncthreads();
        s[t] += x;
        __syncthreads();
    }
    if (i < NEXT) g_rowptr[i] = s[t] - v;
    if (t == SCAN_BS - 1) g_bsum[blockIdx.x] = s[t];
}

__global__ __launch_bounds__(SCAN_BS) void scan2_kernel() {
    __shared__ int s[SCAN_BS];
    int t = threadIdx.x;
    int v = (t < SCAN_NB) ? g_bsum[t] : 0;
    s[t] = v;
    __syncthreads();
#pragma unroll
    for (int off = 1; off < SCAN_BS; off <<= 1) {
        int x = (t >= off) ? s[t - off] : 0;
        __syncthreads();
        s[t] += x;
        __syncthreads();
    }
    if (t < SCAN_NB) g_bsum[t] = s[t] - v;
}

__global__ __launch_bounds__(256) void scan3_kernel() {
    int i = blockIdx.x * blockDim.x + threadIdx.x;
    if (i < NEXT) {
        int rp = g_rowptr[i] + g_bsum[i / SCAN_BS];
        g_rowptr[i] = rp;
        g_tmp[i] = rp;
    }
    if (i == 0) g_rowptr[NEXT] = NNZ_E;
}

__global__ __launch_bounds__(256) void scatter_kernel(const int* __restrict__ rows,
                                                      const int* __restrict__ cols,
                                                      const float* __restrict__ vals) {
    int i = blockIdx.x * blockDim.x + threadIdx.x;
    if (i >= NNZ_E / 4) return;
    int4 r = ((const int4*)rows)[i];
    int4 c = ((const int4*)cols)[i];
    float4 v = ((const float4*)vals)[i];
    int p;
    p = atomicAdd(&g_tmp[r.x], 1); g_epack[p] = make_float2(__int_as_float(c.x), v.x);
    p = atomicAdd(&g_tmp[r.y], 1); g_epack[p] = make_float2(__int_as_float(c.y), v.y);
    p = atomicAdd(&g_tmp[r.z], 1); g_epack[p] = make_float2(__int_as_float(c.z), v.z);
    p = atomicAdd(&g_tmp[r.w], 1); g_epack[p] = make_float2(__int_as_float(c.w), v.w);
}

// ------- pull-mode SpMM + fused epilogue (R4, half-warp per row) ------------
__global__ __launch_bounds__(256) void spmm_fused_kernel(const float* __restrict__ eps, int l) {
    int gid = blockIdx.x * 256 + threadIdx.x;
    int row = gid >> 4;
    int hl = gid & 15;
    if (row >= NEXT) return;

    int s = __ldg(&g_rowptr[row]);
    int e = __ldg(&g_rowptr[row + 1]);
    const float4* __restrict__ T4 = (const float4*)g_T;

    float4 acc = make_float4(0.f, 0.f, 0.f, 0.f);
    float4 acc2 = make_float4(0.f, 0.f, 0.f, 0.f);
    int k = s;
    for (; k + 3 < e; k += 4) {
        float2 p0 = __ldg(&g_epack[k]);
        float2 p1 = __ldg(&g_epack[k + 1]);
        float2 p2 = __ldg(&g_epack[k + 2]);
        float2 p3 = __ldg(&g_epack[k + 3]);
        float4 t0 = __ldg(&T4[__float_as_int(p0.x) * 16 + hl]);
        float4 t1 = __ldg(&T4[__float_as_int(p1.x) * 16 + hl]);
        float4 t2 = __ldg(&T4[__float_as_int(p2.x) * 16 + hl]);
        float4 t3 = __ldg(&T4[__float_as_int(p3.x) * 16 + hl]);
        acc.x += p0.y * t0.x + p1.y * t1.x;
        acc.y += p0.y * t0.y + p1.y * t1.y;
        acc.z += p0.y * t0.z + p1.y * t1.z;
        acc.w += p0.y * t0.w + p1.y * t1.w;
        acc2.x += p2.y * t2.x + p3.y * t3.x;
        acc2.y += p2.y * t2.y + p3.y * t3.y;
        acc2.z += p2.y * t2.z + p3.y * t3.z;
        acc2.w += p2.y * t2.w + p3.y * t3.w;
    }
    for (; k < e; k++) {
        float2 p0 = __ldg(&g_epack[k]);
        float4 t0 = __ldg(&T4[__float_as_int(p0.x) * 16 + hl]);
        acc.x += p0.y * t0.x;
        acc.y += p0.y * t0.y;
        acc.z += p0.y * t0.z;
        acc.w += p0.y * t0.w;
    }
    acc.x += acc2.x; acc.y += acc2.y; acc.z += acc2.z; acc.w += acc2.w;

    int d = row % 3;
    float gate = 1.f + tanhf(__ldg(&eps[l * 3 + d]));
    float4 h = ((const float4*)g_HH)[row * 16 + hl];
    float ex, ey, ez, ew;
    ex = (acc.x > 0.f) ? acc.x : (expf(acc.x) - 1.f);
    ey = (acc.y > 0.f) ? acc.y : (expf(acc.y) - 1.f);
    ez = (acc.z > 0.f) ? acc.z : (expf(acc.z) - 1.f);
    ew = (acc.w > 0.f) ? acc.w : (expf(acc.w) - 1.f);
    float4 r;
    r.x = gate * h.x - ex;
    r.y = gate * h.y - ey;
    r.z = gate * h.z - ez;
    r.w = gate * h.w - ew;
    ((float4*)g_HH)[row * 16 + hl] = r;
}

// ---------------- lin2 + log_softmax ----------------------------------------
__global__ __launch_bounds__(256) void out_kernel(const float* __restrict__ w2,
                                                  const float* __restrict__ b2,
                                                  float* __restrict__ out) {
    __shared__ float sW[40 * 193];
    __shared__ float sH[16 * 192];
    const int tid = threadIdx.x;
    const int gbase = blockIdx.x * 16;

    for (int i = tid; i < 40 * 192; i += 256)
        sW[(i / 192) * 193 + (i % 192)] = w2[i];
    for (int i = tid; i < 16 * 192; i += 256)
        sH[i] = g_HH[gbase * 192 + i];
    __syncthreads();

    const int warp = tid >> 5, lane = tid & 31;
#pragma unroll
    for (int rr = 0; rr < 2; rr++) {
        int row = warp * 2 + rr;
        int g = gbase + row;
        float acc1 = 0.f, acc2 = 0.f;
        const float* hrow = &sH[row * 192];
#pragma unroll 8
        for (int j = 0; j < 192; j++) {
            float hv = hrow[j];
            acc1 += hv * sW[lane * 193 + j];
            if (lane < 8) acc2 += hv * sW[(lane + 32) * 193 + j];
        }
        acc1 += b2[lane];
        float v2 = (lane < 8) ? (acc2 + b2[lane + 32]) : -INFINITY;

        float m = fmaxf(acc1, v2);
#pragma unroll
        for (int off = 16; off; off >>= 1) m = fmaxf(m, __shfl_xor_sync(0xffffffffu, m, off));
        float s = expf(acc1 - m) + ((lane < 8) ? expf(v2 - m) : 0.f);
#pragma unroll
        for (int off = 16; off; off >>= 1) s += __shfl_xor_sync(0xffffffffu, s, off);
        float ls = m + logf(s);

        out[g * OUT_DIM + lane] = acc1 - ls;
        if (lane < 8) out[g * OUT_DIM + 32 + lane] = v2 - ls;
    }
}

// ---------------- launch -----------------------------------------------------
extern "C" void kernel_launch(void* const* d_in, const int* in_sizes, int n_in,
                              void* d_out, int out_size) {
    const float* x   = (const float*)d_in[0];
    const int*   lr  = (const int*)d_in[1];
    const int*   lc  = (const int*)d_in[2];
    const float* lv  = (const float*)d_in[3];
    const float* w1  = (const float*)d_in[4];
    const float* b1  = (const float*)d_in[5];
    const float* lw  = (const float*)d_in[6];   // [L,3,3]
    const float* rw  = (const float*)d_in[7];   // [L,64,64]
    const float* eps = (const float*)d_in[8];   // [L,3,1]
    const float* w2  = (const float*)d_in[9];
    const float* b2  = (const float*)d_in[10];
    float* out = (float*)d_out;

    wsplit_kernel<<<(128 * 192 + 255) / 256, 256>>>(w1);
    lin1_tc_kernel<<<dim3((GNODES + 63) / 64, 3), 256>>>(x, b1);

    // CSR build (once; reused by all layers)
    zero_cnt_kernel<<<(NEXT + 255) / 256, 256>>>();
    hist_kernel<<<(NNZ_E / 4 + 255) / 256, 256>>>(lr);
    scan1_kernel<<<SCAN_NB, SCAN_BS>>>();
    scan2_kernel<<<1, SCAN_BS>>>();
    scan3_kernel<<<(NEXT + 255) / 256, 256>>>();
    scatter_kernel<<<(NNZ_E / 4 + 255) / 256, 256>>>(lr, lc, lv);

    for (int l = 0; l < NLAYERS; l++) {
        transform_kernel<<<NEXT / 48, 256>>>(lw + l * 9, rw + l * 64 * 64);
        spmm_fused_kernel<<<(NEXT * 16 + 255) / 256, 256>>>(eps, l);
    }
    out_kernel<<<GNODES / 16, 256>>>(w2, b2, out);
}

// round 7
// speedup vs baseline: 1.2723x; 1.0937x over previous
#include <cuda_runtime.h>
#include <cuda_bf16.h>
#include <math.h>

#define GNODES 50000
#define DSTALK 3
#define HCH 64
#define IN_DIM 256
#define OUT_DIM 40
#define NLAYERS 4
#define NNZ_E 2400000
#define NEXT (GNODES * DSTALK)   // 150000

#define SCAN_BS 512
#define SCAN_NB ((NEXT + SCAN_BS - 1) / SCAN_BS)   // 293

// ---------------- scratch (static device globals; no allocs) ----------------
__device__ float g_HH[NEXT * HCH];    // h (== h0 between layers), [G,192] view
__device__ float g_T[NEXT * HCH];     // post left+right transform
__device__ int    g_cnt[NEXT];
__device__ int    g_rowptr[NEXT + 1];
__device__ int    g_tmp[NEXT];
__device__ int    g_bsum[SCAN_NB];
__device__ float2 g_epack[NNZ_E];     // packed (col_bits, val) per edge (CSR order)
__device__ unsigned g_W1h[128 * 192]; // W1 split-hi, [kpair][n] pair-packed bf16x2
__device__ unsigned g_W1l[128 * 192]; // W1 split-lo

// ---------------- helpers ----------------------------------------------------
__device__ __forceinline__ void bf16_split2(float a, float b, unsigned& hi, unsigned& lo) {
    __nv_bfloat16 ah = __float2bfloat16(a);
    __nv_bfloat16 bh = __float2bfloat16(b);
    float ar = a - __bfloat162float(ah);
    float br = b - __bfloat162float(bh);
    __nv_bfloat16 al = __float2bfloat16(ar);
    __nv_bfloat16 bl = __float2bfloat16(br);
    hi = ((unsigned)__bfloat16_as_ushort(bh) << 16) | (unsigned)__bfloat16_as_ushort(ah);
    lo = ((unsigned)__bfloat16_as_ushort(bl) << 16) | (unsigned)__bfloat16_as_ushort(al);
}

#define MMA_BF16(d, a, b0, b1)                                              \
    asm volatile("mma.sync.aligned.m16n8k16.row.col.f32.bf16.bf16.f32 "     \
                 "{%0,%1,%2,%3}, {%4,%5,%6,%7}, {%8,%9}, {%0,%1,%2,%3};"    \
                 : "+f"(d[0]), "+f"(d[1]), "+f"(d[2]), "+f"(d[3])           \
                 : "r"(a[0]), "r"(a[1]), "r"(a[2]), "r"(a[3]), "r"(b0), "r"(b1))

// ---------------- W1 split prepass ------------------------------------------
__global__ __launch_bounds__(256) void wsplit_kernel(const float* __restrict__ w) {
    int i = blockIdx.x * 256 + threadIdx.x;    // over 128*192
    if (i >= 128 * 192) return;
    int kk = i / 192, n = i % 192;
    float a = w[n * IN_DIM + 2 * kk];
    float b = w[n * IN_DIM + 2 * kk + 1];
    unsigned hi, lo;
    bf16_split2(a, b, hi, lo);
    g_W1h[i] = hi;
    g_W1l[i] = lo;
}

// ---------------- lin1 (tensor cores, split-bf16): g_HH = elu(x@W1^T + b1) --
// BM=64, BN=64, BK=64. 256 threads = 8 warps (4 m-tiles x 2 n-halves).
// A smem stride 36 -> fragment banks 4q+r (conflict-free).
// B smem stride 72 -> fragment banks 8r+q (conflict-free).
__global__ __launch_bounds__(256) void lin1_tc_kernel(const float* __restrict__ x,
                                                      const float* __restrict__ b) {
    __shared__ unsigned sAh[64][36];
    __shared__ unsigned sAl[64][36];
    __shared__ unsigned sBh[32][72];
    __shared__ unsigned sBl[32][72];
    const int tid = threadIdx.x;
    const int warp = tid >> 5, lane = tid & 31;
    const int bm = blockIdx.x * 64, bn = blockIdx.y * 64;
    const int wm = (warp & 3) * 16;     // m offset of this warp
    const int wn = (warp >> 2) * 32;    // n offset of this warp

    float d[4][4];
#pragma unroll
    for (int j = 0; j < 4; j++)
#pragma unroll
        for (int i = 0; i < 4; i++) d[j][i] = 0.f;

    for (int k0 = 0; k0 < IN_DIM; k0 += 64) {
        // A tile: 64 rows x 64 k  (1024 float4)
        for (int i = tid; i < 1024; i += 256) {
            int r = i >> 4, f4 = i & 15;
            int gr = bm + r;
            float4 v = make_float4(0.f, 0.f, 0.f, 0.f);
            if (gr < GNODES) v = *(const float4*)&x[gr * IN_DIM + k0 + f4 * 4];
            unsigned h0, l0, h1, l1;
            bf16_split2(v.x, v.y, h0, l0);
            bf16_split2(v.z, v.w, h1, l1);
            sAh[r][f4 * 2] = h0;     sAh[r][f4 * 2 + 1] = h1;
            sAl[r][f4 * 2] = l0;     sAl[r][f4 * 2 + 1] = l1;
        }
        // B tile: 32 kpairs x 64 n (from precomputed split)
        for (int i = tid; i < 2048; i += 256) {
            int r = i >> 6, c = i & 63;
            int gi = (k0 / 2 + r) * 192 + bn + c;
            sBh[r][c] = g_W1h[gi];
            sBl[r][c] = g_W1l[gi];
        }
        __syncthreads();

#pragma unroll
        for (int ks = 0; ks < 4; ks++) {
            int ar0 = wm + (lane >> 2);
            int kp = ks * 8 + (lane & 3);
            unsigned ah[4] = { sAh[ar0][kp], sAh[ar0 + 8][kp],
                               sAh[ar0][kp + 4], sAh[ar0 + 8][kp + 4] };
            unsigned al[4] = { sAl[ar0][kp], sAl[ar0 + 8][kp],
                               sAl[ar0][kp + 4], sAl[ar0 + 8][kp + 4] };
#pragma unroll
            for (int j = 0; j < 4; j++) {
                int nc = wn + j * 8 + (lane >> 2);
                int kr = ks * 8 + (lane & 3);
                unsigned bh0 = sBh[kr][nc], bh1 = sBh[kr + 4][nc];
                unsigned bl0 = sBl[kr][nc], bl1 = sBl[kr + 4][nc];
                MMA_BF16(d[j], ah, bh0, bh1);
                MMA_BF16(d[j], ah, bl0, bl1);
                MMA_BF16(d[j], al, bh0, bh1);
            }
        }
        __syncthreads();
    }

    // epilogue: bias + elu + store
#pragma unroll
    for (int j = 0; j < 4; j++) {
        int c = bn + wn + j * 8 + (lane & 3) * 2;   // global n of d[j][0]
        float b0 = __ldg(&b[c]), b1 = __ldg(&b[c + 1]);
        int r0 = bm + wm + (lane >> 2);
        if (r0 < GNODES) {
            float v0 = d[j][0] + b0, v1 = d[j][1] + b1;
            v0 = (v0 > 0.f) ? v0 : (expf(v0) - 1.f);
            v1 = (v1 > 0.f) ? v1 : (expf(v1) - 1.f);
            *(float2*)&g_HH[r0 * 192 + c] = make_float2(v0, v1);
        }
        int r1 = r0 + 8;
        if (r1 < GNODES) {
            float v2 = d[j][2] + b0, v3 = d[j][3] + b1;
            v2 = (v2 > 0.f) ? v2 : (expf(v2) - 1.f);
            v3 = (v3 > 0.f) ? v3 : (expf(v3) - 1.f);
            *(float2*)&g_HH[r1 * 192 + c] = make_float2(v2, v3);
        }
    }
}

// ------- fused left(3x3 stalk) + right(64x64 channel) transform v2 ----------
// 128 threads, 48-row tile; each thread: 12 rows x 2 output channels (cp, cp+32).
__global__ __launch_bounds__(128) void transform_kernel(const float* __restrict__ leftw,
                                                        const float* __restrict__ rightw) {
    __shared__ float sh_h[48 * 68];
    __shared__ float sh_t[48 * 68];
    __shared__ float sh_R[64 * 68];
    const int tid = threadIdx.x;
    const int rowbase = blockIdx.x * 48;   // 3125 blocks * 48 = 150000 exact

    for (int i = tid; i < 1024; i += 128) {
        int row = i >> 4, c4 = i & 15;
        float4 v = ((const float4*)rightw)[i];
        *(float4*)&sh_R[row * 68 + c4 * 4] = v;
    }
    for (int i = tid; i < 768; i += 128) {
        int row = i >> 4, c4 = i & 15;
        float4 v = ((const float4*)g_HH)[(rowbase + row) * 16 + c4];
        *(float4*)&sh_h[row * 68 + c4 * 4] = v;
    }

    float Lw[9];
#pragma unroll
    for (int i = 0; i < 9; i++) Lw[i] = leftw[i];
    __syncthreads();

    for (int i = tid; i < 768; i += 128) {
        int row = i >> 4, c4 = i & 15;
        int e = row % 3;
        int gl = row - e;
        float4 h0 = *(float4*)&sh_h[(gl + 0) * 68 + c4 * 4];
        float4 h1 = *(float4*)&sh_h[(gl + 1) * 68 + c4 * 4];
        float4 h2 = *(float4*)&sh_h[(gl + 2) * 68 + c4 * 4];
        float w0 = Lw[e * 3 + 0], w1 = Lw[e * 3 + 1], w2 = Lw[e * 3 + 2];
        float4 t;
        t.x = w0 * h0.x + w1 * h1.x + w2 * h2.x;
        t.y = w0 * h0.y + w1 * h1.y + w2 * h2.y;
        t.z = w0 * h0.z + w1 * h1.z + w2 * h2.z;
        t.w = w0 * h0.w + w1 * h1.w + w2 * h2.w;
        *(float4*)&sh_t[row * 68 + c4 * 4] = t;
    }
    __syncthreads();

    const int cpa = tid & 31;        // output channel A
    const int cpb = cpa + 32;        // output channel B
    const int rg = tid >> 5;         // 0..3 row group (constant per warp)
    float acca[12], accb[12];
#pragma unroll
    for (int i = 0; i < 12; i++) { acca[i] = 0.f; accb[i] = 0.f; }
#pragma unroll
    for (int c0 = 0; c0 < 64; c0 += 4) {
        float4 rv0 = *(float4*)&sh_R[cpa * 68 + c0];
        float4 rv1 = *(float4*)&sh_R[cpb * 68 + c0];
#pragma unroll
        for (int i = 0; i < 12; i++) {
            float4 tv = *(float4*)&sh_t[(rg + 4 * i) * 68 + c0];  // warp broadcast
            acca[i] += tv.x * rv0.x + tv.y * rv0.y + tv.z * rv0.z + tv.w * rv0.w;
            accb[i] += tv.x * rv1.x + tv.y * rv1.y + tv.z * rv1.z + tv.w * rv1.w;
        }
    }
#pragma unroll
    for (int i = 0; i < 12; i++) {
        int row = rowbase + rg + 4 * i;
        g_T[row * 64 + cpa] = acca[i];
        g_T[row * 64 + cpb] = accb[i];
    }
}

// ---------------- CSR build: zero / hist / scan / scatter -------------------
__global__ __launch_bounds__(256) void zero_cnt_kernel() {
    int i = blockIdx.x * blockDim.x + threadIdx.x;
    if (i < NEXT) g_cnt[i] = 0;
}

__global__ __launch_bounds__(256) void hist_kernel(const int* __restrict__ rows) {
    int i = blockIdx.x * blockDim.x + threadIdx.x;
    if (i >= NNZ_E / 4) return;
    int4 r = ((const int4*)rows)[i];
    atomicAdd(&g_cnt[r.x], 1);
    atomicAdd(&g_cnt[r.y], 1);
    atomicAdd(&g_cnt[r.z], 1);
    atomicAdd(&g_cnt[r.w], 1);
}

__global__ __launch_bounds__(SCAN_BS) void scan1_kernel() {
    __shared__ int s[SCAN_BS];
    int t = threadIdx.x;
    int i = blockIdx.x * SCAN_BS + t;
    int v = (i < NEXT) ? g_cnt[i] : 0;
    s[t] = v;
    __syncthreads();
#pragma unroll
    for (int off = 1; off < SCAN_BS; off <<= 1) {
        int x = (t >= off) ? s[t - off] : 0;
        __syncthreads();
        s[t] += x;
        __syncthreads();
    }
    if (i < NEXT) g_rowptr[i] = s[t] - v;
    if (t == SCAN_BS - 1) g_bsum[blockIdx.x] = s[t];
}

__global__ __launch_bounds__(SCAN_BS) void scan2_kernel() {
    __shared__ int s[SCAN_BS];
    int t = threadIdx.x;
    int v = (t < SCAN_NB) ? g_bsum[t] : 0;
    s[t] = v;
    __syncthreads();
#pragma unroll
    for (int off = 1; off < SCAN_BS; off <<= 1) {
        int x = (t >= off) ? s[t - off] : 0;
        __syncthreads();
        s[t] += x;
        __syncthreads();
    }
    if (t < SCAN_NB) g_bsum[t] = s[t] - v;
}

__global__ __launch_bounds__(256) void scan3_kernel() {
    int i = blockIdx.x * blockDim.x + threadIdx.x;
    if (i < NEXT) {
        int rp = g_rowptr[i] + g_bsum[i / SCAN_BS];
        g_rowptr[i] = rp;
        g_tmp[i] = rp;
    }
    if (i == 0) g_rowptr[NEXT] = NNZ_E;
}

__global__ __launch_bounds__(256) void scatter_kernel(const int* __restrict__ rows,
                                                      const int* __restrict__ cols,
                                                      const float* __restrict__ vals) {
    int i = blockIdx.x * blockDim.x + threadIdx.x;
    if (i >= NNZ_E / 4) return;
    int4 r = ((const int4*)rows)[i];
    int4 c = ((const int4*)cols)[i];
    float4 v = ((const float4*)vals)[i];
    int p;
    p = atomicAdd(&g_tmp[r.x], 1); g_epack[p] = make_float2(__int_as_float(c.x), v.x);
    p = atomicAdd(&g_tmp[r.y], 1); g_epack[p] = make_float2(__int_as_float(c.y), v.y);
    p = atomicAdd(&g_tmp[r.z], 1); g_epack[p] = make_float2(__int_as_float(c.z), v.z);
    p = atomicAdd(&g_tmp[r.w], 1); g_epack[p] = make_float2(__int_as_float(c.w), v.w);
}

// ------- pull-mode SpMM + fused epilogue (half-warp per row) ----------------
__global__ __launch_bounds__(256) void spmm_fused_kernel(const float* __restrict__ eps, int l) {
    int gid = blockIdx.x * 256 + threadIdx.x;
    int row = gid >> 4;
    int hl = gid & 15;
    if (row >= NEXT) return;

    int s = __ldg(&g_rowptr[row]);
    int e = __ldg(&g_rowptr[row + 1]);
    const float4* __restrict__ T4 = (const float4*)g_T;

    float4 acc = make_float4(0.f, 0.f, 0.f, 0.f);
    float4 acc2 = make_float4(0.f, 0.f, 0.f, 0.f);
    int k = s;
    for (; k + 3 < e; k += 4) {
        float2 p0 = __ldg(&g_epack[k]);
        float2 p1 = __ldg(&g_epack[k + 1]);
        float2 p2 = __ldg(&g_epack[k + 2]);
        float2 p3 = __ldg(&g_epack[k + 3]);
        float4 t0 = __ldg(&T4[__float_as_int(p0.x) * 16 + hl]);
        float4 t1 = __ldg(&T4[__float_as_int(p1.x) * 16 + hl]);
        float4 t2 = __ldg(&T4[__float_as_int(p2.x) * 16 + hl]);
        float4 t3 = __ldg(&T4[__float_as_int(p3.x) * 16 + hl]);
        acc.x += p0.y * t0.x + p1.y * t1.x;
        acc.y += p0.y * t0.y + p1.y * t1.y;
        acc.z += p0.y * t0.z + p1.y * t1.z;
        acc.w += p0.y * t0.w + p1.y * t1.w;
        acc2.x += p2.y * t2.x + p3.y * t3.x;
        acc2.y += p2.y * t2.y + p3.y * t3.y;
        acc2.z += p2.y * t2.z + p3.y * t3.z;
        acc2.w += p2.y * t2.w + p3.y * t3.w;
    }
    for (; k < e; k++) {
        float2 p0 = __ldg(&g_epack[k]);
        float4 t0 = __ldg(&T4[__float_as_int(p0.x) * 16 + hl]);
        acc.x += p0.y * t0.x;
        acc.y += p0.y * t0.y;
        acc.z += p0.y * t0.z;
        acc.w += p0.y * t0.w;
    }
    acc.x += acc2.x; acc.y += acc2.y; acc.z += acc2.z; acc.w += acc2.w;

    int d = row % 3;
    float gate = 1.f + tanhf(__ldg(&eps[l * 3 + d]));
    float4 h = ((const float4*)g_HH)[row * 16 + hl];
    float ex, ey, ez, ew;
    ex = (acc.x > 0.f) ? acc.x : (expf(acc.x) - 1.f);
    ey = (acc.y > 0.f) ? acc.y : (expf(acc.y) - 1.f);
    ez = (acc.z > 0.f) ? acc.z : (expf(acc.z) - 1.f);
    ew = (acc.w > 0.f) ? acc.w : (expf(acc.w) - 1.f);
    float4 r;
    r.x = gate * h.x - ex;
    r.y = gate * h.y - ey;
    r.z = gate * h.z - ez;
    r.w = gate * h.w - ew;
    ((float4*)g_HH)[row * 16 + hl] = r;
}

// ---------------- lin2 + log_softmax ----------------------------------------
__global__ __launch_bounds__(256) void out_kernel(const float* __restrict__ w2,
                                                  const float* __restrict__ b2,
                                                  float* __restrict__ out) {
    __shared__ float sW[40 * 193];
    __shared__ float sH[16 * 192];
    const int tid = threadIdx.x;
    const int gbase = blockIdx.x * 16;

    for (int i = tid; i < 40 * 192; i += 256)
        sW[(i / 192) * 193 + (i % 192)] = w2[i];
    for (int i = tid; i < 16 * 192; i += 256)
        sH[i] = g_HH[gbase * 192 + i];
    __syncthreads();

    const int warp = tid >> 5, lane = tid & 31;
#pragma unroll
    for (int rr = 0; rr < 2; rr++) {
        int row = warp * 2 + rr;
        int g = gbase + row;
        float acc1 = 0.f, acc2 = 0.f;
        const float* hrow = &sH[row * 192];
#pragma unroll 8
        for (int j = 0; j < 192; j++) {
            float hv = hrow[j];
            acc1 += hv * sW[lane * 193 + j];
            if (lane < 8) acc2 += hv * sW[(lane + 32) * 193 + j];
        }
        acc1 += b2[lane];
        float v2 = (lane < 8) ? (acc2 + b2[lane + 32]) : -INFINITY;

        float m = fmaxf(acc1, v2);
#pragma unroll
        for (int off = 16; off; off >>= 1) m = fmaxf(m, __shfl_xor_sync(0xffffffffu, m, off));
        float s = expf(acc1 - m) + ((lane < 8) ? expf(v2 - m) : 0.f);
#pragma unroll
        for (int off = 16; off; off >>= 1) s += __shfl_xor_sync(0xffffffffu, s, off);
        float ls = m + logf(s);

        out[g * OUT_DIM + lane] = acc1 - ls;
        if (lane < 8) out[g * OUT_DIM + 32 + lane] = v2 - ls;
    }
}

// ---------------- launch -----------------------------------------------------
extern "C" void kernel_launch(void* const* d_in, const int* in_sizes, int n_in,
                              void* d_out, int out_size) {
    const float* x   = (const float*)d_in[0];
    const int*   lr  = (const int*)d_in[1];
    const int*   lc  = (const int*)d_in[2];
    const float* lv  = (const float*)d_in[3];
    const float* w1  = (const float*)d_in[4];
    const float* b1  = (const float*)d_in[5];
    const float* lw  = (const float*)d_in[6];   // [L,3,3]
    const float* rw  = (const float*)d_in[7];   // [L,64,64]
    const float* eps = (const float*)d_in[8];   // [L,3,1]
    const float* w2  = (const float*)d_in[9];
    const float* b2  = (const float*)d_in[10];
    float* out = (float*)d_out;

    wsplit_kernel<<<(128 * 192 + 255) / 256, 256>>>(w1);
    lin1_tc_kernel<<<dim3((GNODES + 63) / 64, 3), 256>>>(x, b1);

    // CSR build (once; reused by all layers)
    zero_cnt_kernel<<<(NEXT + 255) / 256, 256>>>();
    hist_kernel<<<(NNZ_E / 4 + 255) / 256, 256>>>(lr);
    scan1_kernel<<<SCAN_NB, SCAN_BS>>>();
    scan2_kernel<<<1, SCAN_BS>>>();
    scan3_kernel<<<(NEXT + 255) / 256, 256>>>();
    scatter_kernel<<<(NNZ_E / 4 + 255) / 256, 256>>>(lr, lc, lv);

    for (int l = 0; l < NLAYERS; l++) {
        transform_kernel<<<NEXT / 48, 128>>>(lw + l * 9, rw + l * 64 * 64);
        spmm_fused_kernel<<<(NEXT * 16 + 255) / 256, 256>>>(eps, l);
    }
    out_kernel<<<GNODES / 16, 256>>>(w2, b2, out);
}

// round 8
// speedup vs baseline: 1.4909x; 1.1719x over previous
#include <cuda_runtime.h>
#include <cuda_bf16.h>
#include <math.h>

#define GNODES 50000
#define DSTALK 3
#define HCH 64
#define IN_DIM 256
#define OUT_DIM 40
#define NLAYERS 4
#define NNZ_E 2400000
#define NEXT (GNODES * DSTALK)   // 150000

#define SCAN_BS 512
#define SCAN_NB ((NEXT + SCAN_BS - 1) / SCAN_BS)   // 293

// ---------------- scratch (static device globals; no allocs) ----------------
__device__ float g_HH[NEXT * HCH];    // h (== h0 between layers), [G,192] view
__device__ float g_T[NEXT * HCH];     // post left+right transform
__device__ int    g_cnt[NEXT];
__device__ int    g_rowptr[NEXT + 1];
__device__ int    g_tmp[NEXT];
__device__ int    g_bsum[SCAN_NB];
__device__ float2 g_epack[NNZ_E];     // packed (col_bits, val) per edge (CSR order)
__device__ unsigned g_W1h[128 * 192]; // W1 split-hi, [kpair][n] pair-packed bf16x2
__device__ unsigned g_W1l[128 * 192]; // W1 split-lo
__device__ unsigned g_Rh[NLAYERS * 32 * 64];  // R split-hi, [l][kpair][cp]
__device__ unsigned g_Rl[NLAYERS * 32 * 64];  // R split-lo

// ---------------- helpers ----------------------------------------------------
__device__ __forceinline__ void bf16_split2(float a, float b, unsigned& hi, unsigned& lo) {
    __nv_bfloat16 ah = __float2bfloat16(a);
    __nv_bfloat16 bh = __float2bfloat16(b);
    float ar = a - __bfloat162float(ah);
    float br = b - __bfloat162float(bh);
    __nv_bfloat16 al = __float2bfloat16(ar);
    __nv_bfloat16 bl = __float2bfloat16(br);
    hi = ((unsigned)__bfloat16_as_ushort(bh) << 16) | (unsigned)__bfloat16_as_ushort(ah);
    lo = ((unsigned)__bfloat16_as_ushort(bl) << 16) | (unsigned)__bfloat16_as_ushort(al);
}

#define MMA_BF16(d, a, b0, b1)                                              \
    asm volatile("mma.sync.aligned.m16n8k16.row.col.f32.bf16.bf16.f32 "     \
                 "{%0,%1,%2,%3}, {%4,%5,%6,%7}, {%8,%9}, {%0,%1,%2,%3};"    \
                 : "+f"(d[0]), "+f"(d[1]), "+f"(d[2]), "+f"(d[3])           \
                 : "r"(a[0]), "r"(a[1]), "r"(a[2]), "r"(a[3]), "r"(b0), "r"(b1))

// ---------------- split prepass: W1 + all R matrices ------------------------
__global__ __launch_bounds__(256) void wsplit_kernel(const float* __restrict__ w,
                                                     const float* __restrict__ rw) {
    int i = blockIdx.x * 256 + threadIdx.x;
    if (i < 128 * 192) {
        int kk = i / 192, n = i % 192;
        float a = w[n * IN_DIM + 2 * kk];
        float b = w[n * IN_DIM + 2 * kk + 1];
        unsigned hi, lo;
        bf16_split2(a, b, hi, lo);
        g_W1h[i] = hi;
        g_W1l[i] = lo;
    } else {
        int j = i - 128 * 192;                 // over NLAYERS*32*64
        if (j >= NLAYERS * 32 * 64) return;
        int l = j / (32 * 64);
        int r = j % (32 * 64);
        int kk = r >> 6, cp = r & 63;          // kpair, output channel
        const float* R = rw + l * 64 * 64;     // [cp][c]
        float a = R[cp * 64 + 2 * kk];
        float b = R[cp * 64 + 2 * kk + 1];
        unsigned hi, lo;
        bf16_split2(a, b, hi, lo);
        g_Rh[j] = hi;
        g_Rl[j] = lo;
    }
}

// ---------------- lin1 (tensor cores, split-bf16): g_HH = elu(x@W1^T + b1) --
// BM=64, BN=64, BK=64. 256 threads = 8 warps (4 m-tiles x 2 n-halves).
__global__ __launch_bounds__(256) void lin1_tc_kernel(const float* __restrict__ x,
                                                      const float* __restrict__ b) {
    __shared__ unsigned sAh[64][36];
    __shared__ unsigned sAl[64][36];
    __shared__ unsigned sBh[32][72];
    __shared__ unsigned sBl[32][72];
    const int tid = threadIdx.x;
    const int warp = tid >> 5, lane = tid & 31;
    const int bm = blockIdx.x * 64, bn = blockIdx.y * 64;
    const int wm = (warp & 3) * 16;
    const int wn = (warp >> 2) * 32;

    float d[4][4];
#pragma unroll
    for (int j = 0; j < 4; j++)
#pragma unroll
        for (int i = 0; i < 4; i++) d[j][i] = 0.f;

    for (int k0 = 0; k0 < IN_DIM; k0 += 64) {
        for (int i = tid; i < 1024; i += 256) {
            int r = i >> 4, f4 = i & 15;
            int gr = bm + r;
            float4 v = make_float4(0.f, 0.f, 0.f, 0.f);
            if (gr < GNODES) v = *(const float4*)&x[gr * IN_DIM + k0 + f4 * 4];
            unsigned h0, l0, h1, l1;
            bf16_split2(v.x, v.y, h0, l0);
            bf16_split2(v.z, v.w, h1, l1);
            sAh[r][f4 * 2] = h0;     sAh[r][f4 * 2 + 1] = h1;
            sAl[r][f4 * 2] = l0;     sAl[r][f4 * 2 + 1] = l1;
        }
        for (int i = tid; i < 2048; i += 256) {
            int r = i >> 6, c = i & 63;
            int gi = (k0 / 2 + r) * 192 + bn + c;
            sBh[r][c] = g_W1h[gi];
            sBl[r][c] = g_W1l[gi];
        }
        __syncthreads();

#pragma unroll
        for (int ks = 0; ks < 4; ks++) {
            int ar0 = wm + (lane >> 2);
            int kp = ks * 8 + (lane & 3);
            unsigned ah[4] = { sAh[ar0][kp], sAh[ar0 + 8][kp],
                               sAh[ar0][kp + 4], sAh[ar0 + 8][kp + 4] };
            unsigned al[4] = { sAl[ar0][kp], sAl[ar0 + 8][kp],
                               sAl[ar0][kp + 4], sAl[ar0 + 8][kp + 4] };
#pragma unroll
            for (int j = 0; j < 4; j++) {
                int nc = wn + j * 8 + (lane >> 2);
                int kr = ks * 8 + (lane & 3);
                unsigned bh0 = sBh[kr][nc], bh1 = sBh[kr + 4][nc];
                unsigned bl0 = sBl[kr][nc], bl1 = sBl[kr + 4][nc];
                MMA_BF16(d[j], ah, bh0, bh1);
                MMA_BF16(d[j], ah, bl0, bl1);
                MMA_BF16(d[j], al, bh0, bh1);
            }
        }
        __syncthreads();
    }

#pragma unroll
    for (int j = 0; j < 4; j++) {
        int c = bn + wn + j * 8 + (lane & 3) * 2;
        float b0 = __ldg(&b[c]), b1 = __ldg(&b[c + 1]);
        int r0 = bm + wm + (lane >> 2);
        if (r0 < GNODES) {
            float v0 = d[j][0] + b0, v1 = d[j][1] + b1;
            v0 = (v0 > 0.f) ? v0 : (expf(v0) - 1.f);
            v1 = (v1 > 0.f) ? v1 : (expf(v1) - 1.f);
            *(float2*)&g_HH[r0 * 192 + c] = make_float2(v0, v1);
        }
        int r1 = r0 + 8;
        if (r1 < GNODES) {
            float v2 = d[j][2] + b0, v3 = d[j][3] + b1;
            v2 = (v2 > 0.f) ? v2 : (expf(v2) - 1.f);
            v3 = (v3 > 0.f) ? v3 : (expf(v3) - 1.f);
            *(float2*)&g_HH[r1 * 192 + c] = make_float2(v2, v3);
        }
    }
}

// ------- transform (tensor cores): g_T = leftmix(g_HH) @ R^T ----------------
// BM=48 (16 node triples), N=64, K=64. 192 threads = 6 warps (3m x 2n).
__global__ __launch_bounds__(192) void transform_tc_kernel(const float* __restrict__ leftw,
                                                           int l) {
    __shared__ unsigned sAh[48][36];
    __shared__ unsigned sAl[48][36];
    __shared__ unsigned sBh[32][72];
    __shared__ unsigned sBl[32][72];
    const int tid = threadIdx.x;
    const int warp = tid >> 5, lane = tid & 31;
    const int rowbase = blockIdx.x * 48;        // 3125 blocks * 48 = 150000
    const int wm = (warp % 3) * 16;
    const int wn = (warp / 3) * 32;

    // B tile: precomputed R split, [kpair][cp]
    for (int i = tid; i < 2048; i += 192) {
        int r = i >> 6, c = i & 63;
        int gi = l * 32 * 64 + i;
        sBh[r][c] = g_Rh[gi];
        sBl[r][c] = g_Rl[gi];
    }

    float Lw[9];
#pragma unroll
    for (int i = 0; i < 9; i++) Lw[i] = __ldg(&leftw[i]);

    // A tile: load HH triples, leftmix in registers, split to bf16 hi/lo
    const float4* HH4 = (const float4*)g_HH;
    for (int i = tid; i < 256; i += 192) {       // 16 triples x 16 f4
        int node = i >> 4, f4 = i & 15;
        int r3 = rowbase + node * 3;
        float4 h0 = HH4[(r3 + 0) * 16 + f4];
        float4 h1 = HH4[(r3 + 1) * 16 + f4];
        float4 h2 = HH4[(r3 + 2) * 16 + f4];
#pragma unroll
        for (int dd = 0; dd < 3; dd++) {
            float w0 = Lw[3 * dd], w1 = Lw[3 * dd + 1], w2 = Lw[3 * dd + 2];
            float tx = w0 * h0.x + w1 * h1.x + w2 * h2.x;
            float ty = w0 * h0.y + w1 * h1.y + w2 * h2.y;
            float tz = w0 * h0.z + w1 * h1.z + w2 * h2.z;
            float tw = w0 * h0.w + w1 * h1.w + w2 * h2.w;
            unsigned p0h, p0l, p1h, p1l;
            bf16_split2(tx, ty, p0h, p0l);
            bf16_split2(tz, tw, p1h, p1l);
            int r = node * 3 + dd;
            sAh[r][f4 * 2] = p0h;  sAh[r][f4 * 2 + 1] = p1h;
            sAl[r][f4 * 2] = p0l;  sAl[r][f4 * 2 + 1] = p1l;
        }
    }
    __syncthreads();

    float d[4][4];
#pragma unroll
    for (int j = 0; j < 4; j++)
#pragma unroll
        for (int i = 0; i < 4; i++) d[j][i] = 0.f;

#pragma unroll
    for (int ks = 0; ks < 4; ks++) {
        int ar0 = wm + (lane >> 2);
        int kp = ks * 8 + (lane & 3);
        unsigned ah[4] = { sAh[ar0][kp], sAh[ar0 + 8][kp],
                           sAh[ar0][kp + 4], sAh[ar0 + 8][kp + 4] };
        unsigned al[4] = { sAl[ar0][kp], sAl[ar0 + 8][kp],
                           sAl[ar0][kp + 4], sAl[ar0 + 8][kp + 4] };
#pragma unroll
        for (int j = 0; j < 4; j++) {
            int nc = wn + j * 8 + (lane >> 2);
            int kr = ks * 8 + (lane & 3);
            unsigned bh0 = sBh[kr][nc], bh1 = sBh[kr + 4][nc];
            unsigned bl0 = sBl[kr][nc], bl1 = sBl[kr + 4][nc];
            MMA_BF16(d[j], ah, bh0, bh1);
            MMA_BF16(d[j], ah, bl0, bl1);
            MMA_BF16(d[j], al, bh0, bh1);
        }
    }

#pragma unroll
    for (int j = 0; j < 4; j++) {
        int c = wn + j * 8 + (lane & 3) * 2;
        int r0 = rowbase + wm + (lane >> 2);
        *(float2*)&g_T[r0 * 64 + c] = make_float2(d[j][0], d[j][1]);
        int r1 = r0 + 8;
        *(float2*)&g_T[r1 * 64 + c] = make_float2(d[j][2], d[j][3]);
    }
}

// ---------------- CSR build: zero / hist / scan / scatter -------------------
__global__ __launch_bounds__(256) void zero_cnt_kernel() {
    int i = blockIdx.x * blockDim.x + threadIdx.x;
    if (i < NEXT) g_cnt[i] = 0;
}

__global__ __launch_bounds__(256) void hist_kernel(const int* __restrict__ rows) {
    int i = blockIdx.x * blockDim.x + threadIdx.x;
    if (i >= NNZ_E / 4) return;
    int4 r = ((const int4*)rows)[i];
    atomicAdd(&g_cnt[r.x], 1);
    atomicAdd(&g_cnt[r.y], 1);
    atomicAdd(&g_cnt[r.z], 1);
    atomicAdd(&g_cnt[r.w], 1);
}

__global__ __launch_bounds__(SCAN_BS) void scan1_kernel() {
    __shared__ int s[SCAN_BS];
    int t = threadIdx.x;
    int i = blockIdx.x * SCAN_BS + t;
    int v = (i < NEXT) ? g_cnt[i] : 0;
    s[t] = v;
    __syncthreads();
#pragma unroll
    for (int off = 1; off < SCAN_BS; off <<= 1) {
        int x = (t >= off) ? s[t - off] : 0;
        __syncthreads();
        s[t] += x;
        __syncthreads();
    }
    if (i < NEXT) g_rowptr[i] = s[t] - v;
    if (t == SCAN_BS - 1) g_bsum[blockIdx.x] = s[t];
}

__global__ __launch_bounds__(SCAN_BS) void scan2_kernel() {
    __shared__ int s[SCAN_BS];
    int t = threadIdx.x;
    int v = (t < SCAN_NB) ? g_bsum[t] : 0;
    s[t] = v;
    __syncthreads();
#pragma unroll
    for (int off = 1; off < SCAN_BS; off <<= 1) {
        int x = (t >= off) ? s[t - off] : 0;
        __syncthreads();
        s[t] += x;
        __syncthreads();
    }
    if (t < SCAN_NB) g_bsum[t] = s[t] - v;
}

__global__ __launch_bounds__(256) void scan3_kernel() {
    int i = blockIdx.x * blockDim.x + threadIdx.x;
    if (i < NEXT) {
        int rp = g_rowptr[i] + g_bsum[i / SCAN_BS];
        g_rowptr[i] = rp;
        g_tmp[i] = rp;
    }
    if (i == 0) g_rowptr[NEXT] = NNZ_E;
}

__global__ __launch_bounds__(256) void scatter_kernel(const int* __restrict__ rows,
                                                      const int* __restrict__ cols,
                                                      const float* __restrict__ vals) {
    int i = blockIdx.x * blockDim.x + threadIdx.x;
    if (i >= NNZ_E / 4) return;
    int4 r = ((const int4*)rows)[i];
    int4 c = ((const int4*)cols)[i];
    float4 v = ((const float4*)vals)[i];
    int p;
    p = atomicAdd(&g_tmp[r.x], 1); g_epack[p] = make_float2(__int_as_float(c.x), v.x);
    p = atomicAdd(&g_tmp[r.y], 1); g_epack[p] = make_float2(__int_as_float(c.y), v.y);
    p = atomicAdd(&g_tmp[r.z], 1); g_epack[p] = make_float2(__int_as_float(c.z), v.z);
    p = atomicAdd(&g_tmp[r.w], 1); g_epack[p] = make_float2(__int_as_float(c.w), v.w);
}

// ------- pull-mode SpMM + fused epilogue (half-warp per row) ----------------
__global__ __launch_bounds__(256) void spmm_fused_kernel(const float* __restrict__ eps, int l) {
    int gid = blockIdx.x * 256 + threadIdx.x;
    int row = gid >> 4;
    int hl = gid & 15;
    if (row >= NEXT) return;

    int s = __ldg(&g_rowptr[row]);
    int e = __ldg(&g_rowptr[row + 1]);
    const float4* __restrict__ T4 = (const float4*)g_T;

    float4 acc = make_float4(0.f, 0.f, 0.f, 0.f);
    float4 acc2 = make_float4(0.f, 0.f, 0.f, 0.f);
    int k = s;
    for (; k + 3 < e; k += 4) {
        float2 p0 = __ldg(&g_epack[k]);
        float2 p1 = __ldg(&g_epack[k + 1]);
        float2 p2 = __ldg(&g_epack[k + 2]);
        float2 p3 = __ldg(&g_epack[k + 3]);
        float4 t0 = __ldg(&T4[__float_as_int(p0.x) * 16 + hl]);
        float4 t1 = __ldg(&T4[__float_as_int(p1.x) * 16 + hl]);
        float4 t2 = __ldg(&T4[__float_as_int(p2.x) * 16 + hl]);
        float4 t3 = __ldg(&T4[__float_as_int(p3.x) * 16 + hl]);
        acc.x += p0.y * t0.x + p1.y * t1.x;
        acc.y += p0.y * t0.y + p1.y * t1.y;
        acc.z += p0.y * t0.z + p1.y * t1.z;
        acc.w += p0.y * t0.w + p1.y * t1.w;
        acc2.x += p2.y * t2.x + p3.y * t3.x;
        acc2.y += p2.y * t2.y + p3.y * t3.y;
        acc2.z += p2.y * t2.z + p3.y * t3.z;
        acc2.w += p2.y * t2.w + p3.y * t3.w;
    }
    for (; k < e; k++) {
        float2 p0 = __ldg(&g_epack[k]);
        float4 t0 = __ldg(&T4[__float_as_int(p0.x) * 16 + hl]);
        acc.x += p0.y * t0.x;
        acc.y += p0.y * t0.y;
        acc.z += p0.y * t0.z;
        acc.w += p0.y * t0.w;
    }
    acc.x += acc2.x; acc.y += acc2.y; acc.z += acc2.z; acc.w += acc2.w;

    int d = row % 3;
    float gate = 1.f + tanhf(__ldg(&eps[l * 3 + d]));
    float4 h = ((const float4*)g_HH)[row * 16 + hl];
    float ex, ey, ez, ew;
    ex = (acc.x > 0.f) ? acc.x : (expf(acc.x) - 1.f);
    ey = (acc.y > 0.f) ? acc.y : (expf(acc.y) - 1.f);
    ez = (acc.z > 0.f) ? acc.z : (expf(acc.z) - 1.f);
    ew = (acc.w > 0.f) ? acc.w : (expf(acc.w) - 1.f);
    float4 r;
    r.x = gate * h.x - ex;
    r.y = gate * h.y - ey;
    r.z = gate * h.z - ez;
    r.w = gate * h.w - ew;
    ((float4*)g_HH)[row * 16 + hl] = r;
}

// ---------------- lin2 + log_softmax ----------------------------------------
__global__ __launch_bounds__(256) void out_kernel(const float* __restrict__ w2,
                                                  const float* __restrict__ b2,
                                                  float* __restrict__ out) {
    __shared__ float sW[40 * 193];
    __shared__ float sH[16 * 192];
    const int tid = threadIdx.x;
    const int gbase = blockIdx.x * 16;

    for (int i = tid; i < 40 * 192; i += 256)
        sW[(i / 192) * 193 + (i % 192)] = w2[i];
    for (int i = tid; i < 16 * 192; i += 256)
        sH[i] = g_HH[gbase * 192 + i];
    __syncthreads();

    const int warp = tid >> 5, lane = tid & 31;
#pragma unroll
    for (int rr = 0; rr < 2; rr++) {
        int row = warp * 2 + rr;
        int g = gbase + row;
        float acc1 = 0.f, acc2 = 0.f;
        const float* hrow = &sH[row * 192];
#pragma unroll 8
        for (int j = 0; j < 192; j++) {
            float hv = hrow[j];
            acc1 += hv * sW[lane * 193 + j];
            if (lane < 8) acc2 += hv * sW[(lane + 32) * 193 + j];
        }
        acc1 += b2[lane];
        float v2 = (lane < 8) ? (acc2 + b2[lane + 32]) : -INFINITY;

        float m = fmaxf(acc1, v2);
#pragma unroll
        for (int off = 16; off; off >>= 1) m = fmaxf(m, __shfl_xor_sync(0xffffffffu, m, off));
        float s = expf(acc1 - m) + ((lane < 8) ? expf(v2 - m) : 0.f);
#pragma unroll
        for (int off = 16; off; off >>= 1) s += __shfl_xor_sync(0xffffffffu, s, off);
        float ls = m + logf(s);

        out[g * OUT_DIM + lane] = acc1 - ls;
        if (lane < 8) out[g * OUT_DIM + 32 + lane] = v2 - ls;
    }
}

// ---------------- launch -----------------------------------------------------
extern "C" void kernel_launch(void* const* d_in, const int* in_sizes, int n_in,
                              void* d_out, int out_size) {
    const float* x   = (const float*)d_in[0];
    const int*   lr  = (const int*)d_in[1];
    const int*   lc  = (const int*)d_in[2];
    const float* lv  = (const float*)d_in[3];
    const float* w1  = (const float*)d_in[4];
    const float* b1  = (const float*)d_in[5];
    const float* lw  = (const float*)d_in[6];   // [L,3,3]
    const float* rw  = (const float*)d_in[7];   // [L,64,64]
    const float* eps = (const float*)d_in[8];   // [L,3,1]
    const float* w2  = (const float*)d_in[9];
    const float* b2  = (const float*)d_in[10];
    float* out = (float*)d_out;

    // Order chosen so lin1_tc is the 4th launch (ncu profiles launch #4).
    zero_cnt_kernel<<<(NEXT + 255) / 256, 256>>>();
    hist_kernel<<<(NNZ_E / 4 + 255) / 256, 256>>>(lr);
    wsplit_kernel<<<(128 * 192 + NLAYERS * 32 * 64 + 255) / 256, 256>>>(w1, rw);
    lin1_tc_kernel<<<dim3((GNODES + 63) / 64, 3), 256>>>(x, b1);
    scan1_kernel<<<SCAN_NB, SCAN_BS>>>();
    scan2_kernel<<<1, SCAN_BS>>>();
    scan3_kernel<<<(NEXT + 255) / 256, 256>>>();
    scatter_kernel<<<(NNZ_E / 4 + 255) / 256, 256>>>(lr, lc, lv);

    for (int l = 0; l < NLAYERS; l++) {
        transform_tc_kernel<<<NEXT / 48, 192>>>(lw + l * 9, l);
        spmm_fused_kernel<<<(NEXT * 16 + 255) / 256, 256>>>(eps, l);
    }
    out_kernel<<<GNODES / 16, 256>>>(w2, b2, out);
}

// round 9
// speedup vs baseline: 1.4920x; 1.0007x over previous
#include <cuda_runtime.h>
#include <cuda_bf16.h>
#include <math.h>

#define GNODES 50000
#define DSTALK 3
#define HCH 64
#define IN_DIM 256
#define OUT_DIM 40
#define NLAYERS 4
#define NNZ_E 2400000
#define NEXT (GNODES * DSTALK)   // 150000

#define SCAN_BS 512
#define SCAN_NB ((NEXT + SCAN_BS - 1) / SCAN_BS)   // 293

// ---------------- scratch (static device globals; no allocs) ----------------
__device__ float g_HH[NEXT * HCH];    // h (== h0 between layers), [G,192] view
__device__ float g_T[NEXT * HCH];     // post left+right transform
__device__ int    g_cnt[NEXT];
__device__ int    g_rowptr[NEXT + 1];
__device__ int    g_tmp[NEXT];
__device__ int    g_bsum[SCAN_NB];
__device__ float2 g_epack[NNZ_E];     // packed (col_bits, val) per edge (CSR order)
__device__ unsigned g_W1h[128 * 192]; // W1 split-hi, [kpair][n] pair-packed bf16x2
__device__ unsigned g_W1l[128 * 192]; // W1 split-lo
__device__ unsigned g_Rh[NLAYERS * 32 * 64];  // R split-hi, [l][kpair][cp]
__device__ unsigned g_Rl[NLAYERS * 32 * 64];  // R split-lo

// ---------------- helpers ----------------------------------------------------
__device__ __forceinline__ void bf16_split2(float a, float b, unsigned& hi, unsigned& lo) {
    __nv_bfloat16 ah = __float2bfloat16(a);
    __nv_bfloat16 bh = __float2bfloat16(b);
    float ar = a - __bfloat162float(ah);
    float br = b - __bfloat162float(bh);
    __nv_bfloat16 al = __float2bfloat16(ar);
    __nv_bfloat16 bl = __float2bfloat16(br);
    hi = ((unsigned)__bfloat16_as_ushort(bh) << 16) | (unsigned)__bfloat16_as_ushort(ah);
    lo = ((unsigned)__bfloat16_as_ushort(bl) << 16) | (unsigned)__bfloat16_as_ushort(al);
}

#define MMA_BF16(d, a, b0, b1)                                              \
    asm volatile("mma.sync.aligned.m16n8k16.row.col.f32.bf16.bf16.f32 "     \
                 "{%0,%1,%2,%3}, {%4,%5,%6,%7}, {%8,%9}, {%0,%1,%2,%3};"    \
                 : "+f"(d[0]), "+f"(d[1]), "+f"(d[2]), "+f"(d[3])           \
                 : "r"(a[0]), "r"(a[1]), "r"(a[2]), "r"(a[3]), "r"(b0), "r"(b1))

// ---------------- split prepass: W1 + all R matrices ------------------------
__global__ __launch_bounds__(256) void wsplit_kernel(const float* __restrict__ w,
                                                     const float* __restrict__ rw) {
    int i = blockIdx.x * 256 + threadIdx.x;
    if (i < 128 * 192) {
        int kk = i / 192, n = i % 192;
        float a = w[n * IN_DIM + 2 * kk];
        float b = w[n * IN_DIM + 2 * kk + 1];
        unsigned hi, lo;
        bf16_split2(a, b, hi, lo);
        g_W1h[i] = hi;
        g_W1l[i] = lo;
    } else {
        int j = i - 128 * 192;                 // over NLAYERS*32*64
        if (j >= NLAYERS * 32 * 64) return;
        int l = j / (32 * 64);
        int r = j % (32 * 64);
        int kk = r >> 6, cp = r & 63;          // kpair, output channel
        const float* R = rw + l * 64 * 64;     // [cp][c]
        float a = R[cp * 64 + 2 * kk];
        float b = R[cp * 64 + 2 * kk + 1];
        unsigned hi, lo;
        bf16_split2(a, b, hi, lo);
        g_Rh[j] = hi;
        g_Rl[j] = lo;
    }
}

// ---------------- lin1 (tensor cores, split-bf16): g_HH = elu(x@W1^T + b1) --
// BM=64, BN=64, BK=64. 256 threads = 8 warps (4 m-tiles x 2 n-halves).
__global__ __launch_bounds__(256) void lin1_tc_kernel(const float* __restrict__ x,
                                                      const float* __restrict__ b) {
    __shared__ unsigned sAh[64][36];
    __shared__ unsigned sAl[64][36];
    __shared__ unsigned sBh[32][72];
    __shared__ unsigned sBl[32][72];
    const int tid = threadIdx.x;
    const int warp = tid >> 5, lane = tid & 31;
    const int bm = blockIdx.x * 64, bn = blockIdx.y * 64;
    const int wm = (warp & 3) * 16;
    const int wn = (warp >> 2) * 32;

    float d[4][4];
#pragma unroll
    for (int j = 0; j < 4; j++)
#pragma unroll
        for (int i = 0; i < 4; i++) d[j][i] = 0.f;

    for (int k0 = 0; k0 < IN_DIM; k0 += 64) {
        for (int i = tid; i < 1024; i += 256) {
            int r = i >> 4, f4 = i & 15;
            int gr = bm + r;
            float4 v = make_float4(0.f, 0.f, 0.f, 0.f);
            if (gr < GNODES) v = *(const float4*)&x[gr * IN_DIM + k0 + f4 * 4];
            unsigned h0, l0, h1, l1;
            bf16_split2(v.x, v.y, h0, l0);
            bf16_split2(v.z, v.w, h1, l1);
            sAh[r][f4 * 2] = h0;     sAh[r][f4 * 2 + 1] = h1;
            sAl[r][f4 * 2] = l0;     sAl[r][f4 * 2 + 1] = l1;
        }
        for (int i = tid; i < 2048; i += 256) {
            int r = i >> 6, c = i & 63;
            int gi = (k0 / 2 + r) * 192 + bn + c;
            sBh[r][c] = g_W1h[gi];
            sBl[r][c] = g_W1l[gi];
        }
        __syncthreads();

#pragma unroll
        for (int ks = 0; ks < 4; ks++) {
            int ar0 = wm + (lane >> 2);
            int kp = ks * 8 + (lane & 3);
            unsigned ah[4] = { sAh[ar0][kp], sAh[ar0 + 8][kp],
                               sAh[ar0][kp + 4], sAh[ar0 + 8][kp + 4] };
            unsigned al[4] = { sAl[ar0][kp], sAl[ar0 + 8][kp],
                               sAl[ar0][kp + 4], sAl[ar0 + 8][kp + 4] };
#pragma unroll
            for (int j = 0; j < 4; j++) {
                int nc = wn + j * 8 + (lane >> 2);
                int kr = ks * 8 + (lane & 3);
                unsigned bh0 = sBh[kr][nc], bh1 = sBh[kr + 4][nc];
                unsigned bl0 = sBl[kr][nc], bl1 = sBl[kr + 4][nc];
                MMA_BF16(d[j], ah, bh0, bh1);
                MMA_BF16(d[j], ah, bl0, bl1);
                MMA_BF16(d[j], al, bh0, bh1);
            }
        }
        __syncthreads();
    }

#pragma unroll
    for (int j = 0; j < 4; j++) {
        int c = bn + wn + j * 8 + (lane & 3) * 2;
        float b0 = __ldg(&b[c]), b1 = __ldg(&b[c + 1]);
        int r0 = bm + wm + (lane >> 2);
        if (r0 < GNODES) {
            float v0 = d[j][0] + b0, v1 = d[j][1] + b1;
            v0 = (v0 > 0.f) ? v0 : (expf(v0) - 1.f);
            v1 = (v1 > 0.f) ? v1 : (expf(v1) - 1.f);
            *(float2*)&g_HH[r0 * 192 + c] = make_float2(v0, v1);
        }
        int r1 = r0 + 8;
        if (r1 < GNODES) {
            float v2 = d[j][2] + b0, v3 = d[j][3] + b1;
            v2 = (v2 > 0.f) ? v2 : (expf(v2) - 1.f);
            v3 = (v3 > 0.f) ? v3 : (expf(v3) - 1.f);
            *(float2*)&g_HH[r1 * 192 + c] = make_float2(v2, v3);
        }
    }
}

// ------- transform (tensor cores): g_T = leftmix(g_HH) @ R^T ----------------
// BM=48 (16 node triples), N=64, K=64. 192 threads = 6 warps (3m x 2n).
__global__ __launch_bounds__(192) void transform_tc_kernel(const float* __restrict__ leftw,
                                                           int l) {
    __shared__ unsigned sAh[48][36];
    __shared__ unsigned sAl[48][36];
    __shared__ unsigned sBh[32][72];
    __shared__ unsigned sBl[32][72];
    const int tid = threadIdx.x;
    const int warp = tid >> 5, lane = tid & 31;
    const int rowbase = blockIdx.x * 48;        // 3125 blocks * 48 = 150000
    const int wm = (warp % 3) * 16;
    const int wn = (warp / 3) * 32;

    // B tile: precomputed R split, [kpair][cp]
    for (int i = tid; i < 2048; i += 192) {
        int r = i >> 6, c = i & 63;
        int gi = l * 32 * 64 + i;
        sBh[r][c] = g_Rh[gi];
        sBl[r][c] = g_Rl[gi];
    }

    float Lw[9];
#pragma unroll
    for (int i = 0; i < 9; i++) Lw[i] = __ldg(&leftw[i]);

    // A tile: load HH triples, leftmix in registers, split to bf16 hi/lo
    const float4* HH4 = (const float4*)g_HH;
    for (int i = tid; i < 256; i += 192) {       // 16 triples x 16 f4
        int node = i >> 4, f4 = i & 15;
        int r3 = rowbase + node * 3;
        float4 h0 = HH4[(r3 + 0) * 16 + f4];
        float4 h1 = HH4[(r3 + 1) * 16 + f4];
        float4 h2 = HH4[(r3 + 2) * 16 + f4];
#pragma unroll
        for (int dd = 0; dd < 3; dd++) {
            float w0 = Lw[3 * dd], w1 = Lw[3 * dd + 1], w2 = Lw[3 * dd + 2];
            float tx = w0 * h0.x + w1 * h1.x + w2 * h2.x;
            float ty = w0 * h0.y + w1 * h1.y + w2 * h2.y;
            float tz = w0 * h0.z + w1 * h1.z + w2 * h2.z;
            float tw = w0 * h0.w + w1 * h1.w + w2 * h2.w;
            unsigned p0h, p0l, p1h, p1l;
            bf16_split2(tx, ty, p0h, p0l);
            bf16_split2(tz, tw, p1h, p1l);
            int r = node * 3 + dd;
            sAh[r][f4 * 2] = p0h;  sAh[r][f4 * 2 + 1] = p1h;
            sAl[r][f4 * 2] = p0l;  sAl[r][f4 * 2 + 1] = p1l;
        }
    }
    __syncthreads();

    float d[4][4];
#pragma unroll
    for (int j = 0; j < 4; j++)
#pragma unroll
        for (int i = 0; i < 4; i++) d[j][i] = 0.f;

#pragma unroll
    for (int ks = 0; ks < 4; ks++) {
        int ar0 = wm + (lane >> 2);
        int kp = ks * 8 + (lane & 3);
        unsigned ah[4] = { sAh[ar0][kp], sAh[ar0 + 8][kp],
                           sAh[ar0][kp + 4], sAh[ar0 + 8][kp + 4] };
        unsigned al[4] = { sAl[ar0][kp], sAl[ar0 + 8][kp],
                           sAl[ar0][kp + 4], sAl[ar0 + 8][kp + 4] };
#pragma unroll
        for (int j = 0; j < 4; j++) {
            int nc = wn + j * 8 + (lane >> 2);
            int kr = ks * 8 + (lane & 3);
            unsigned bh0 = sBh[kr][nc], bh1 = sBh[kr + 4][nc];
            unsigned bl0 = sBl[kr][nc], bl1 = sBl[kr + 4][nc];
            MMA_BF16(d[j], ah, bh0, bh1);
            MMA_BF16(d[j], ah, bl0, bl1);
            MMA_BF16(d[j], al, bh0, bh1);
        }
    }

#pragma unroll
    for (int j = 0; j < 4; j++) {
        int c = wn + j * 8 + (lane & 3) * 2;
        int r0 = rowbase + wm + (lane >> 2);
        *(float2*)&g_T[r0 * 64 + c] = make_float2(d[j][0], d[j][1]);
        int r1 = r0 + 8;
        *(float2*)&g_T[r1 * 64 + c] = make_float2(d[j][2], d[j][3]);
    }
}

// ---------------- CSR build: zero / hist / scan / scatter -------------------
__global__ __launch_bounds__(256) void zero_cnt_kernel() {
    int i = blockIdx.x * blockDim.x + threadIdx.x;
    if (i < NEXT) g_cnt[i] = 0;
}

__global__ __launch_bounds__(256) void hist_kernel(const int* __restrict__ rows) {
    int i = blockIdx.x * blockDim.x + threadIdx.x;
    if (i >= NNZ_E / 4) return;
    int4 r = ((const int4*)rows)[i];
    atomicAdd(&g_cnt[r.x], 1);
    atomicAdd(&g_cnt[r.y], 1);
    atomicAdd(&g_cnt[r.z], 1);
    atomicAdd(&g_cnt[r.w], 1);
}

__global__ __launch_bounds__(SCAN_BS) void scan1_kernel() {
    __shared__ int s[SCAN_BS];
    int t = threadIdx.x;
    int i = blockIdx.x * SCAN_BS + t;
    int v = (i < NEXT) ? g_cnt[i] : 0;
    s[t] = v;
    __syncthreads();
#pragma unroll
    for (int off = 1; off < SCAN_BS; off <<= 1) {
        int x = (t >= off) ? s[t - off] : 0;
        __syncthreads();
        s[t] += x;
        __syncthreads();
    }
    if (i < NEXT) g_rowptr[i] = s[t] - v;
    if (t == SCAN_BS - 1) g_bsum[blockIdx.x] = s[t];
}

__global__ __launch_bounds__(SCAN_BS) void scan2_kernel() {
    __shared__ int s[SCAN_BS];
    int t = threadIdx.x;
    int v = (t < SCAN_NB) ? g_bsum[t] : 0;
    s[t] = v;
    __syncthreads();
#pragma unroll
    for (int off = 1; off < SCAN_BS; off <<= 1) {
        int x = (t >= off) ? s[t - off] : 0;
        __syncthreads();
        s[t] += x;
        __syncthreads();
    }
    if (t < SCAN_NB) g_bsum[t] = s[t] - v;
}

__global__ __launch_bounds__(256) void scan3_kernel() {
    int i = blockIdx.x * blockDim.x + threadIdx.x;
    if (i < NEXT) {
        int rp = g_rowptr[i] + g_bsum[i / SCAN_BS];
        g_rowptr[i] = rp;
        g_tmp[i] = rp;
    }
    if (i == 0) g_rowptr[NEXT] = NNZ_E;
}

__global__ __launch_bounds__(256) void scatter_kernel(const int* __restrict__ rows,
                                                      const int* __restrict__ cols,
                                                      const float* __restrict__ vals) {
    int i = blockIdx.x * blockDim.x + threadIdx.x;
    if (i >= NNZ_E / 4) return;
    int4 r = ((const int4*)rows)[i];
    int4 c = ((const int4*)cols)[i];
    float4 v = ((const float4*)vals)[i];
    int p;
    p = atomicAdd(&g_tmp[r.x], 1); g_epack[p] = make_float2(__int_as_float(c.x), v.x);
    p = atomicAdd(&g_tmp[r.y], 1); g_epack[p] = make_float2(__int_as_float(c.y), v.y);
    p = atomicAdd(&g_tmp[r.z], 1); g_epack[p] = make_float2(__int_as_float(c.z), v.z);
    p = atomicAdd(&g_tmp[r.w], 1); g_epack[p] = make_float2(__int_as_float(c.w), v.w);
}

// ------- pull-mode SpMM + fused epilogue (half-warp per row) ----------------
__global__ __launch_bounds__(256) void spmm_fused_kernel(const float* __restrict__ eps, int l) {
    int gid = blockIdx.x * 256 + threadIdx.x;
    int row = gid >> 4;
    int hl = gid & 15;
    if (row >= NEXT) return;

    int s = __ldg(&g_rowptr[row]);
    int e = __ldg(&g_rowptr[row + 1]);
    const float4* __restrict__ T4 = (const float4*)g_T;

    float4 acc = make_float4(0.f, 0.f, 0.f, 0.f);
    float4 acc2 = make_float4(0.f, 0.f, 0.f, 0.f);
    int k = s;
    for (; k + 3 < e; k += 4) {
        float2 p0 = __ldg(&g_epack[k]);
        float2 p1 = __ldg(&g_epack[k + 1]);
        float2 p2 = __ldg(&g_epack[k + 2]);
        float2 p3 = __ldg(&g_epack[k + 3]);
        float4 t0 = __ldg(&T4[__float_as_int(p0.x) * 16 + hl]);
        float4 t1 = __ldg(&T4[__float_as_int(p1.x) * 16 + hl]);
        float4 t2 = __ldg(&T4[__float_as_int(p2.x) * 16 + hl]);
        float4 t3 = __ldg(&T4[__float_as_int(p3.x) * 16 + hl]);
        acc.x += p0.y * t0.x + p1.y * t1.x;
        acc.y += p0.y * t0.y + p1.y * t1.y;
        acc.z += p0.y * t0.z + p1.y * t1.z;
        acc.w += p0.y * t0.w + p1.y * t1.w;
        acc2.x += p2.y * t2.x + p3.y * t3.x;
        acc2.y += p2.y * t2.y + p3.y * t3.y;
        acc2.z += p2.y * t2.z + p3.y * t3.z;
        acc2.w += p2.y * t2.w + p3.y * t3.w;
    }
    for (; k < e; k++) {
        float2 p0 = __ldg(&g_epack[k]);
        float4 t0 = __ldg(&T4[__float_as_int(p0.x) * 16 + hl]);
        acc.x += p0.y * t0.x;
        acc.y += p0.y * t0.y;
        acc.z += p0.y * t0.z;
        acc.w += p0.y * t0.w;
    }
    acc.x += acc2.x; acc.y += acc2.y; acc.z += acc2.z; acc.w += acc2.w;

    int d = row % 3;
    float gate = 1.f + tanhf(__ldg(&eps[l * 3 + d]));
    float4 h = ((const float4*)g_HH)[row * 16 + hl];
    float ex, ey, ez, ew;
    ex = (acc.x > 0.f) ? acc.x : (expf(acc.x) - 1.f);
    ey = (acc.y > 0.f) ? acc.y : (expf(acc.y) - 1.f);
    ez = (acc.z > 0.f) ? acc.z : (expf(acc.z) - 1.f);
    ew = (acc.w > 0.f) ? acc.w : (expf(acc.w) - 1.f);
    float4 r;
    r.x = gate * h.x - ex;
    r.y = gate * h.y - ey;
    r.z = gate * h.z - ez;
    r.w = gate * h.w - ew;
    ((float4*)g_HH)[row * 16 + hl] = r;
}

// ---------------- lin2 + log_softmax ----------------------------------------
__global__ __launch_bounds__(256) void out_kernel(const float* __restrict__ w2,
                                                  const float* __restrict__ b2,
                                                  float* __restrict__ out) {
    __shared__ float sW[40 * 193];
    __shared__ float sH[16 * 192];
    const int tid = threadIdx.x;
    const int gbase = blockIdx.x * 16;

    for (int i = tid; i < 40 * 192; i += 256)
        sW[(i / 192) * 193 + (i % 192)] = w2[i];
    for (int i = tid; i < 16 * 192; i += 256)
        sH[i] = g_HH[gbase * 192 + i];
    __syncthreads();

    const int warp = tid >> 5, lane = tid & 31;
#pragma unroll
    for (int rr = 0; rr < 2; rr++) {
        int row = warp * 2 + rr;
        int g = gbase + row;
        float acc1 = 0.f, acc2 = 0.f;
        const float* hrow = &sH[row * 192];
#pragma unroll 8
        for (int j = 0; j < 192; j++) {
            float hv = hrow[j];
            acc1 += hv * sW[lane * 193 + j];
            if (lane < 8) acc2 += hv * sW[(lane + 32) * 193 + j];
        }
        acc1 += b2[lane];
        float v2 = (lane < 8) ? (acc2 + b2[lane + 32]) : -INFINITY;

        float m = fmaxf(acc1, v2);
#pragma unroll
        for (int off = 16; off; off >>= 1) m = fmaxf(m, __shfl_xor_sync(0xffffffffu, m, off));
        float s = expf(acc1 - m) + ((lane < 8) ? expf(v2 - m) : 0.f);
#pragma unroll
        for (int off = 16; off; off >>= 1) s += __shfl_xor_sync(0xffffffffu, s, off);
        float ls = m + logf(s);

        out[g * OUT_DIM + lane] = acc1 - ls;
        if (lane < 8) out[g * OUT_DIM + 32 + lane] = v2 - ls;
    }
}

// ---------------- launch -----------------------------------------------------
extern "C" void kernel_launch(void* const* d_in, const int* in_sizes, int n_in,
                              void* d_out, int out_size) {
    const float* x   = (const float*)d_in[0];
    const int*   lr  = (const int*)d_in[1];
    const int*   lc  = (const int*)d_in[2];
    const float* lv  = (const float*)d_in[3];
    const float* w1  = (const float*)d_in[4];
    const float* b1  = (const float*)d_in[5];
    const float* lw  = (const float*)d_in[6];   // [L,3,3]
    const float* rw  = (const float*)d_in[7];   // [L,64,64]
    const float* eps = (const float*)d_in[8];   // [L,3,1]
    const float* w2  = (const float*)d_in[9];
    const float* b2  = (const float*)d_in[10];
    float* out = (float*)d_out;

    // Order chosen so lin1_tc is the 4th launch (ncu profiles launch #4).
    zero_cnt_kernel<<<(NEXT + 255) / 256, 256>>>();
    hist_kernel<<<(NNZ_E / 4 + 255) / 256, 256>>>(lr);
    wsplit_kernel<<<(128 * 192 + NLAYERS * 32 * 64 + 255) / 256, 256>>>(w1, rw);
    lin1_tc_kernel<<<dim3((GNODES + 63) / 64, 3), 256>>>(x, b1);
    scan1_kernel<<<SCAN_NB, SCAN_BS>>>();
    scan2_kernel<<<1, SCAN_BS>>>();
    scan3_kernel<<<(NEXT + 255) / 256, 256>>>();
    scatter_kernel<<<(NNZ_E / 4 + 255) / 256, 256>>>(lr, lc, lv);

    for (int l = 0; l < NLAYERS; l++) {
        transform_tc_kernel<<<NEXT / 48, 192>>>(lw + l * 9, l);
        spmm_fused_kernel<<<(NEXT * 16 + 255) / 256, 256>>>(eps, l);
    }
    out_kernel<<<GNODES / 16, 256>>>(w2, b2, out);
}